// round 5
// baseline (speedup 1.0000x reference)
#include <cuda_runtime.h>
#include <cuda_bf16.h>
#include <cstdint>

#define NN   3072
#define INF  512
#define NH   8
#define HD   64
#define OF   512   // NH*HD
#define MW   96    // NN/32 mask words per row
#define KT   32    // attn j tile (one mask word)
#define MT   128   // attn i tile per CTA
#define NTILES (NN / KT)

// ---------------- scratch ----------------
__device__ float         g_h[NN * OF];
__device__ float         g_P[NH * NN];
__device__ float         g_p[NH * NN];
__device__ float         g_Q[NH * NN];
__device__ float         g_q[NH * NN];
__device__ unsigned      g_mask[NN * MW];            // row-major [i][jword]
__device__ __nv_bfloat16 g_hT1[NH * HD * NN];        // hi split, [h][d][n]
__device__ __nv_bfloat16 g_hT2[NH * HD * NN];        // lo split

__device__ __forceinline__ uint32_t smem_u32(const void* p) {
    uint32_t a;
    asm("{ .reg .u64 t; cvta.to.shared.u64 t, %1; cvt.u32.u64 %0, t; }" : "=r"(a) : "l"(p));
    return a;
}

__device__ __forceinline__ void mma_bf16(float* c, const uint32_t* a, uint32_t b0, uint32_t b1) {
    asm volatile(
        "mma.sync.aligned.m16n8k16.row.col.f32.bf16.bf16.f32 "
        "{%0,%1,%2,%3}, {%4,%5,%6,%7}, {%8,%9}, {%0,%1,%2,%3};"
        : "+f"(c[0]), "+f"(c[1]), "+f"(c[2]), "+f"(c[3])
        : "r"(a[0]), "r"(a[1]), "r"(a[2]), "r"(a[3]), "r"(b0), "r"(b1));
}

__device__ __forceinline__ void ldmx4(uint32_t* r, uint32_t addr) {
    asm volatile("ldmatrix.sync.aligned.m8n8.x4.shared.b16 {%0,%1,%2,%3}, [%4];"
                 : "=r"(r[0]), "=r"(r[1]), "=r"(r[2]), "=r"(r[3]) : "r"(addr));
}

// pack two fp32 -> bf16x2 (lo half = w0, hi half = w1) + residual pack
__device__ __forceinline__ void split2(float w0, float w1, uint32_t& hi, uint32_t& lo) {
    uint32_t h;
    asm("cvt.rn.bf16x2.f32 %0, %1, %2;" : "=r"(h) : "f"(w1), "f"(w0));
    float r0 = w0 - __uint_as_float(h << 16);
    float r1 = w1 - __uint_as_float(h & 0xffff0000u);
    uint32_t l;
    asm("cvt.rn.bf16x2.f32 %0, %1, %2;" : "=r"(l) : "f"(r1), "f"(r0));
    hi = h; lo = l;
}

// ---------------- Kernel 1: g_h = X @ W^T  (bf16-split HMMA) ----------------
// CTA = 64m x 128n, BK=32, grid (48, 4). 8 warps as 2(m) x 4(n), warp = 32m x 32n.
// 3 products: Xh*Wh + Xh*Wl + Xl*Wh, fp32 accumulate.
__global__ __launch_bounds__(256) void gemm_kernel(const float* __restrict__ X,
                                                   const float* __restrict__ Wm) {
    __shared__ __align__(16) unsigned char Ah[2][64 * 64];    // 8KB
    __shared__ __align__(16) unsigned char Al[2][64 * 64];
    __shared__ __align__(16) unsigned char Bh[2][128 * 64];   // 16KB
    __shared__ __align__(16) unsigned char Bl[2][128 * 64];

    const int tid = threadIdx.x;
    const int w   = tid >> 5;
    const int L   = tid & 31;
    const int bm  = blockIdx.x * 64;
    const int bn  = blockIdx.y * 128;

    // staging roles
    const int arow   = tid >> 2;        // 0..63
    const int achunk = tid & 3;         // 8-k chunk
    const uint32_t aoff = (uint32_t)(arow * 64 + ((achunk ^ ((arow >> 1) & 3)) << 4));
    const int brow0 = tid >> 2;         // task s: row = s*64 + brow0
    const int bchunk = tid & 3;

    // warp tile
    const int warp_m = (w >> 2) * 32;
    const int warp_n = (w & 3) * 32;

    float acc[2][4][4];
#pragma unroll
    for (int mg = 0; mg < 2; mg++)
#pragma unroll
        for (int ng = 0; ng < 4; ng++)
#pragma unroll
            for (int k = 0; k < 4; k++) acc[mg][ng][k] = 0.f;

    // gmem load for iter 0
    float4 xa0, xa1, wb0[2], wb1[2];
    {
        const float4* xp = (const float4*)(X + (size_t)(bm + arow) * INF + achunk * 8);
        xa0 = xp[0]; xa1 = xp[1];
#pragma unroll
        for (int s = 0; s < 2; s++) {
            const float4* wp = (const float4*)(Wm + (size_t)(bn + s * 64 + brow0) * INF + bchunk * 8);
            wb0[s] = wp[0]; wb1[s] = wp[1];
        }
    }

    for (int it = 0; it < INF / 32; it++) {
        const int buf = it & 1;
        // store staged tile (split to bf16 hi/lo, swizzled)
        {
            uint32_t h0,h1,h2,h3,l0,l1,l2,l3;
            split2(xa0.x, xa0.y, h0, l0); split2(xa0.z, xa0.w, h1, l1);
            split2(xa1.x, xa1.y, h2, l2); split2(xa1.z, xa1.w, h3, l3);
            *(uint4*)&Ah[buf][aoff] = make_uint4(h0,h1,h2,h3);
            *(uint4*)&Al[buf][aoff] = make_uint4(l0,l1,l2,l3);
#pragma unroll
            for (int s = 0; s < 2; s++) {
                const int br = s * 64 + brow0;
                const uint32_t boff = (uint32_t)(br * 64 + ((bchunk ^ ((br >> 1) & 3)) << 4));
                split2(wb0[s].x, wb0[s].y, h0, l0); split2(wb0[s].z, wb0[s].w, h1, l1);
                split2(wb1[s].x, wb1[s].y, h2, l2); split2(wb1[s].z, wb1[s].w, h3, l3);
                *(uint4*)&Bh[buf][boff] = make_uint4(h0,h1,h2,h3);
                *(uint4*)&Bl[buf][boff] = make_uint4(l0,l1,l2,l3);
            }
        }
        __syncthreads();

        // prefetch next iter's gmem
        if (it + 1 < INF / 32) {
            const int k0 = (it + 1) * 32;
            const float4* xp = (const float4*)(X + (size_t)(bm + arow) * INF + k0 + achunk * 8);
            xa0 = xp[0]; xa1 = xp[1];
#pragma unroll
            for (int s = 0; s < 2; s++) {
                const float4* wp = (const float4*)(Wm + (size_t)(bn + s * 64 + brow0) * INF + k0 + bchunk * 8);
                wb0[s] = wp[0]; wb1[s] = wp[1];
            }
        }

        // ---- fragments ----
        const uint32_t aAh = smem_u32(&Ah[buf][0]);
        const uint32_t aAl = smem_u32(&Al[buf][0]);
        const uint32_t aBh = smem_u32(&Bh[buf][0]);
        const uint32_t aBl = smem_u32(&Bl[buf][0]);

        uint32_t bh[4][4], bl[4][4];
#pragma unroll
        for (int ng = 0; ng < 4; ng++) {
            const int row = warp_n + ng * 8 + (L & 7);
            const int ch  = L >> 3;
            const uint32_t off = (uint32_t)(row * 64 + ((ch ^ ((row >> 1) & 3)) << 4));
            ldmx4(bh[ng], aBh + off);
            ldmx4(bl[ng], aBl + off);
        }
        uint32_t ah[2][2][4], al[2][2][4];   // [mg][ks][4]
#pragma unroll
        for (int mg = 0; mg < 2; mg++)
#pragma unroll
            for (int ks = 0; ks < 2; ks++) {
                const int mat = L >> 3;
                const int row = warp_m + mg * 16 + (L & 7) + (mat & 1) * 8;
                const int ch  = ks * 2 + (mat >> 1);
                const uint32_t off = (uint32_t)(row * 64 + ((ch ^ ((row >> 1) & 3)) << 4));
                ldmx4(ah[mg][ks], aAh + off);
                ldmx4(al[mg][ks], aAl + off);
            }

#pragma unroll
        for (int mg = 0; mg < 2; mg++)
#pragma unroll
            for (int ng = 0; ng < 4; ng++) {
#pragma unroll
                for (int ks = 0; ks < 2; ks++) {
                    mma_bf16(acc[mg][ng], ah[mg][ks], bh[ng][2*ks], bh[ng][2*ks+1]);
                    mma_bf16(acc[mg][ng], ah[mg][ks], bl[ng][2*ks], bl[ng][2*ks+1]);
                    mma_bf16(acc[mg][ng], al[mg][ks], bh[ng][2*ks], bh[ng][2*ks+1]);
                }
            }
        __syncthreads();
    }

    // epilogue: write fp32 h
#pragma unroll
    for (int mg = 0; mg < 2; mg++)
#pragma unroll
        for (int ng = 0; ng < 4; ng++) {
            const int row = bm + warp_m + mg * 16 + (L >> 2);
            const int col = bn + warp_n + ng * 8 + (L & 3) * 2;
            *(float2*)(g_h + (size_t)row * OF + col)       = make_float2(acc[mg][ng][0], acc[mg][ng][1]);
            *(float2*)(g_h + (size_t)(row + 8) * OF + col) = make_float2(acc[mg][ng][2], acc[mg][ng][3]);
        }
}

// ---------------- Kernel 2: per-(node,head) exp coefficients ----------------
__global__ void coef_kernel(const float* __restrict__ a_src,
                            const float* __restrict__ a_dst) {
    int idx = blockIdx.x * blockDim.x + threadIdx.x;   // h*NN + n
    int h = idx / NN;
    int n = idx % NN;
    const float4* hv = (const float4*)(g_h + (size_t)n * OF + h * HD);
    const float4* as = (const float4*)(a_src + h * HD);
    const float4* ad = (const float4*)(a_dst + h * HD);
    float s = 0.f, t = 0.f;
#pragma unroll
    for (int k = 0; k < 16; k++) {
        float4 hh = hv[k], va = as[k], vd = ad[k];
        s += hh.x * va.x + hh.y * va.y + hh.z * va.z + hh.w * va.w;
        t += hh.x * vd.x + hh.y * vd.y + hh.z * vd.z + hh.w * vd.w;
    }
    g_P[idx] = __expf(s);
    g_p[idx] = __expf(0.2f * s);
    g_Q[idx] = __expf(t);
    g_q[idx] = __expf(0.2f * t);
}

// ---------------- Kernel 3: adjacency (+diag) bitmask — int4 loads + shfl pack ----------------
// Warp handles 128 cols of one row: lane loads int4 (4 cols) -> nibble; 3 shfl_xor
// ORs assemble 32-bit words in lanes; lanes 0,8,16,24 store 4 words.
__global__ __launch_bounds__(256) void mask_kernel(const int* __restrict__ adj) {
    const int gw = (blockIdx.x * blockDim.x + threadIdx.x) >> 5;
    const int L  = threadIdx.x & 31;
    const int i  = gw / (NN / 128);
    const int sp = gw % (NN / 128);
    const int c0 = sp * 128 + L * 4;
    const int4 v = *(const int4*)(adj + (size_t)i * NN + c0);
    unsigned nib = ((v.x != 0 || c0     == i) ? 1u : 0u)
                 | ((v.y != 0 || c0 + 1 == i) ? 2u : 0u)
                 | ((v.z != 0 || c0 + 2 == i) ? 4u : 0u)
                 | ((v.w != 0 || c0 + 3 == i) ? 8u : 0u);
    unsigned val = nib << ((L & 7) * 4);
    val |= __shfl_xor_sync(0xffffffffu, val, 1);
    val |= __shfl_xor_sync(0xffffffffu, val, 2);
    val |= __shfl_xor_sync(0xffffffffu, val, 4);
    if ((L & 7) == 0) g_mask[i * MW + sp * 4 + (L >> 3)] = val;
}

// ---------------- Kernel 3b: transpose + bf16 hi/lo split of h ----------------
__global__ __launch_bounds__(256) void hsplit_kernel() {
    __shared__ float tl[32][65];
    const int h  = blockIdx.y;
    const int n0 = blockIdx.x * 32;
    const int t  = threadIdx.x;
    {
        int r  = t >> 3;
        int c8 = (t & 7) * 8;
        const float* src = g_h + (size_t)(n0 + r) * OF + h * HD + c8;
        float4 v0 = *(const float4*)src;
        float4 v1 = *(const float4*)(src + 4);
        tl[r][c8+0] = v0.x; tl[r][c8+1] = v0.y; tl[r][c8+2] = v0.z; tl[r][c8+3] = v0.w;
        tl[r][c8+4] = v1.x; tl[r][c8+5] = v1.y; tl[r][c8+6] = v1.z; tl[r][c8+7] = v1.w;
    }
    __syncthreads();
    const int d  = t >> 2;
    const int ns = (t & 3) * 8;
    uint32_t hi[4], lo[4];
#pragma unroll
    for (int k = 0; k < 4; k++) {
        float va = tl[ns + 2*k][d];
        float vb = tl[ns + 2*k + 1][d];
        split2(va, vb, hi[k], lo[k]);
    }
    size_t o = (size_t)(h * HD + d) * NN + n0 + ns;
    *(uint4*)(g_hT1 + o) = make_uint4(hi[0], hi[1], hi[2], hi[3]);
    *(uint4*)(g_hT2 + o) = make_uint4(lo[0], lo[1], lo[2], lo[3]);
}

// ---------------- Kernel 4: HMMA masked softmax-aggregate ----------------
__global__ __launch_bounds__(256) void attn_kernel(float* __restrict__ out) {
    __shared__ __align__(16) unsigned char Bsm[2][2][HD * 64];
    __shared__ __align__(8)  float2 QQ[2][KT];

    const int tid  = threadIdx.x;
    const int w    = tid >> 5;
    const int L    = tid & 31;
    const int head = blockIdx.y;
    const int i0   = blockIdx.x * MT;

    const int sd   = tid >> 2;
    const int sseg = tid & 3;
    const __nv_bfloat16* h1p = g_hT1 + (size_t)(head * HD + sd) * NN;
    const __nv_bfloat16* h2p = g_hT2 + (size_t)(head * HD + sd) * NN;
    const uint32_t soff = (uint32_t)(sd * 64 + ((sseg ^ ((sd >> 1) & 3)) << 4));

    const int r  = L >> 2;
    const int cb = (L & 3) * 2;
    const int irow0 = i0 + w * 16 + r;
    const int irow1 = irow0 + 8;
    const float P0 = g_P[head * NN + irow0];
    const float p0 = g_p[head * NN + irow0];
    const float P1 = g_P[head * NN + irow1];
    const float p1 = g_p[head * NN + irow1];
    const unsigned* mrow0 = g_mask + (size_t)irow0 * MW;
    const unsigned* mrow1 = g_mask + (size_t)irow1 * MW;

    const uint32_t b1base = smem_u32(&Bsm[0][0][0]);

    float acc[8][4];
#pragma unroll
    for (int n = 0; n < 8; n++)
#pragma unroll
        for (int k = 0; k < 4; k++) acc[n][k] = 0.f;
    float z0 = 0.f, z1 = 0.f;

    uint4 nb1 = *(const uint4*)(h1p + sseg * 8);
    uint4 nb2 = *(const uint4*)(h2p + sseg * 8);
    unsigned nm0 = mrow0[0];
    unsigned nm1 = mrow1[0];
    float nQ = 0.f, nq = 0.f;
    if (tid < KT) {
        nQ = g_Q[head * NN + tid];
        nq = g_q[head * NN + tid];
    }

    for (int t = 0; t < NTILES; t++) {
        const int buf = t & 1;
        *(uint4*)&Bsm[buf][0][soff] = nb1;
        *(uint4*)&Bsm[buf][1][soff] = nb2;
        if (tid < KT) QQ[buf][tid] = make_float2(nQ, nq);
        const unsigned mw0 = nm0;
        const unsigned mw1 = nm1;
        __syncthreads();

        if (t + 1 < NTILES) {
            const int j0 = (t + 1) * KT;
            nb1 = *(const uint4*)(h1p + j0 + sseg * 8);
            nb2 = *(const uint4*)(h2p + j0 + sseg * 8);
            nm0 = mrow0[t + 1];
            nm1 = mrow1[t + 1];
            if (tid < KT) {
                nQ = g_Q[head * NN + j0 + tid];
                nq = g_q[head * NN + j0 + tid];
            }
        }

        uint32_t A1[2][4], A2[2][4];
#pragma unroll
        for (int ks = 0; ks < 2; ks++) {
            const int jb = cb + ks * 16;
            float2 q0 = QQ[buf][jb];
            float2 q1 = QQ[buf][jb + 1];
            float2 q2 = QQ[buf][jb + 8];
            float2 q3 = QQ[buf][jb + 9];
            float w00 = fmaxf(P0 * q0.x, p0 * q0.y); w00 = ((mw0 >> jb)       & 1u) ? w00 : 0.f;
            float w01 = fmaxf(P0 * q1.x, p0 * q1.y); w01 = ((mw0 >> (jb + 1)) & 1u) ? w01 : 0.f;
            float w02 = fmaxf(P0 * q2.x, p0 * q2.y); w02 = ((mw0 >> (jb + 8)) & 1u) ? w02 : 0.f;
            float w03 = fmaxf(P0 * q3.x, p0 * q3.y); w03 = ((mw0 >> (jb + 9)) & 1u) ? w03 : 0.f;
            float w10 = fmaxf(P1 * q0.x, p1 * q0.y); w10 = ((mw1 >> jb)       & 1u) ? w10 : 0.f;
            float w11 = fmaxf(P1 * q1.x, p1 * q1.y); w11 = ((mw1 >> (jb + 1)) & 1u) ? w11 : 0.f;
            float w12 = fmaxf(P1 * q2.x, p1 * q2.y); w12 = ((mw1 >> (jb + 8)) & 1u) ? w12 : 0.f;
            float w13 = fmaxf(P1 * q3.x, p1 * q3.y); w13 = ((mw1 >> (jb + 9)) & 1u) ? w13 : 0.f;
            z0 += (w00 + w01) + (w02 + w03);
            z1 += (w10 + w11) + (w12 + w13);
            split2(w00, w01, A1[ks][0], A2[ks][0]);
            split2(w10, w11, A1[ks][1], A2[ks][1]);
            split2(w02, w03, A1[ks][2], A2[ks][2]);
            split2(w12, w13, A1[ks][3], A2[ks][3]);
        }

        const uint32_t bufofs = (uint32_t)buf * (2 * HD * 64);
        const int ld_d = (L & 7);
        const int ld_m = (L >> 3);
#pragma unroll
        for (int nt = 0; nt < 8; nt++) {
            const int d = nt * 8 + ld_d;
            const uint32_t addr1 = b1base + bufofs + (uint32_t)(d * 64 + ((ld_m ^ ((d >> 1) & 3)) << 4));
            const uint32_t addr2 = addr1 + (uint32_t)(HD * 64);
            uint32_t B1[4], B2[4];
            ldmx4(B1, addr1);
            ldmx4(B2, addr2);
            mma_bf16(acc[nt], A1[0], B1[0], B1[1]);
            mma_bf16(acc[nt], A1[1], B1[2], B1[3]);
            mma_bf16(acc[nt], A1[0], B2[0], B2[1]);
            mma_bf16(acc[nt], A1[1], B2[2], B2[3]);
            mma_bf16(acc[nt], A2[0], B1[0], B1[1]);
            mma_bf16(acc[nt], A2[1], B1[2], B1[3]);
        }
    }

    z0 += __shfl_xor_sync(0xffffffffu, z0, 1);
    z0 += __shfl_xor_sync(0xffffffffu, z0, 2);
    z1 += __shfl_xor_sync(0xffffffffu, z1, 1);
    z1 += __shfl_xor_sync(0xffffffffu, z1, 2);
    const float iz0 = 1.0f / z0;
    const float iz1 = 1.0f / z1;

    float* o0 = out + (size_t)irow0 * OF + head * HD + cb;
    float* o1 = out + (size_t)irow1 * OF + head * HD + cb;
#pragma unroll
    for (int nt = 0; nt < 8; nt++) {
        *(float2*)(o0 + nt * 8) = make_float2(acc[nt][0] * iz0, acc[nt][1] * iz0);
        *(float2*)(o1 + nt * 8) = make_float2(acc[nt][2] * iz1, acc[nt][3] * iz1);
    }
}

// ---------------- launch ----------------
extern "C" void kernel_launch(void* const* d_in, const int* in_sizes, int n_in,
                              void* d_out, int out_size) {
    const float* x     = (const float*)d_in[0];
    const int*   adj   = (const int*)d_in[1];
    const float* W     = (const float*)d_in[2];
    const float* a_src = (const float*)d_in[3];
    const float* a_dst = (const float*)d_in[4];
    float* out = (float*)d_out;

    gemm_kernel<<<dim3(NN / 64, OF / 128), 256>>>(x, W);
    coef_kernel<<<(NH * NN) / 256, 256>>>(a_src, a_dst);
    hsplit_kernel<<<dim3(NN / 32, NH), 256>>>();
    mask_kernel<<<(NN * (NN / 128) * 32) / 256, 256>>>(adj);
    attn_kernel<<<dim3(NN / MT, NH), 256>>>(out);
}

// round 6
// speedup vs baseline: 1.5353x; 1.5353x over previous
#include <cuda_runtime.h>
#include <cuda_bf16.h>
#include <cstdint>

#define NN   3072
#define INF  512
#define NH   8
#define HD   64
#define OF   512   // NH*HD
#define MW   96    // mask words per row
#define KT   32    // attn j tile
#define MT   128   // attn i tile per CTA
#define NTILES (NN / KT)

// ---------------- scratch ----------------
__device__ float         g_h[NN * OF];
__device__ float         g_P[NH * NN];
__device__ float         g_p[NH * NN];
__device__ float         g_Q[NH * NN];
__device__ float         g_q[NH * NN];
__device__ unsigned      g_mask[NN * MW];
__device__ __nv_bfloat16 g_hT1[NH * HD * NN];      // [h][d][n] hi
__device__ __nv_bfloat16 g_hT2[NH * HD * NN];      // lo
__device__ __nv_bfloat16 g_X1[NN * INF];           // X hi split
__device__ __nv_bfloat16 g_X2[NN * INF];           // X lo
__device__ __nv_bfloat16 g_W1[OF * INF];           // W hi
__device__ __nv_bfloat16 g_W2[OF * INF];           // W lo

__device__ __forceinline__ uint32_t smem_u32(const void* p) {
    uint32_t a;
    asm("{ .reg .u64 t; cvta.to.shared.u64 t, %1; cvt.u32.u64 %0, t; }" : "=r"(a) : "l"(p));
    return a;
}

__device__ __forceinline__ void mma_bf16(float* c, const uint32_t* a, uint32_t b0, uint32_t b1) {
    asm volatile(
        "mma.sync.aligned.m16n8k16.row.col.f32.bf16.bf16.f32 "
        "{%0,%1,%2,%3}, {%4,%5,%6,%7}, {%8,%9}, {%0,%1,%2,%3};"
        : "+f"(c[0]), "+f"(c[1]), "+f"(c[2]), "+f"(c[3])
        : "r"(a[0]), "r"(a[1]), "r"(a[2]), "r"(a[3]), "r"(b0), "r"(b1));
}

__device__ __forceinline__ void ldmx4(uint32_t* r, uint32_t addr) {
    asm volatile("ldmatrix.sync.aligned.m8n8.x4.shared.b16 {%0,%1,%2,%3}, [%4];"
                 : "=r"(r[0]), "=r"(r[1]), "=r"(r[2]), "=r"(r[3]) : "r"(addr));
}

__device__ __forceinline__ void split2(float w0, float w1, uint32_t& hi, uint32_t& lo) {
    uint32_t h;
    asm("cvt.rn.bf16x2.f32 %0, %1, %2;" : "=r"(h) : "f"(w1), "f"(w0));
    float r0 = w0 - __uint_as_float(h << 16);
    float r1 = w1 - __uint_as_float(h & 0xffff0000u);
    uint32_t l;
    asm("cvt.rn.bf16x2.f32 %0, %1, %2;" : "=r"(l) : "f"(r1), "f"(r0));
    hi = h; lo = l;
}

// ---------------- Kernel 0: fp32 -> bf16 hi/lo split (one pass) ----------------
__global__ __launch_bounds__(256) void fsplit_kernel(const float* __restrict__ src,
                                                     __nv_bfloat16* __restrict__ dhi,
                                                     __nv_bfloat16* __restrict__ dlo) {
    const int idx = (blockIdx.x * blockDim.x + threadIdx.x) * 4;
    float4 v = *(const float4*)(src + idx);
    uint32_t h0, h1, l0, l1;
    split2(v.x, v.y, h0, l0);
    split2(v.z, v.w, h1, l1);
    *(uint2*)(dhi + idx) = make_uint2(h0, h1);
    *(uint2*)(dlo + idx) = make_uint2(l0, l1);
}

// ---------------- Kernel 1: g_h = X @ W^T (bf16-split HMMA, pre-split inputs) ----------------
// CTA = 64m x 128n, BK=32, grid (48, 4). 8 warps 2(m) x 4(n), warp = 32m x 32n.
__global__ __launch_bounds__(256) void gemm_kernel() {
    __shared__ __align__(16) unsigned char Ah[2][64 * 64];
    __shared__ __align__(16) unsigned char Al[2][64 * 64];
    __shared__ __align__(16) unsigned char Bh[2][128 * 64];
    __shared__ __align__(16) unsigned char Bl[2][128 * 64];

    const int tid = threadIdx.x;
    const int w   = tid >> 5;
    const int L   = tid & 31;
    const int bm  = blockIdx.x * 64;
    const int bn  = blockIdx.y * 128;

    const int arow   = tid >> 2;
    const int achunk = tid & 3;
    const uint32_t aoff = (uint32_t)(arow * 64 + ((achunk ^ ((arow >> 1) & 3)) << 4));
    const int brow0  = tid >> 2;
    const int bchunk = tid & 3;
    const uint32_t boff0 = (uint32_t)(brow0 * 64 + ((bchunk ^ ((brow0 >> 1) & 3)) << 4));
    const int brow1  = 64 + brow0;
    const uint32_t boff1 = (uint32_t)(brow1 * 64 + ((bchunk ^ ((brow1 >> 1) & 3)) << 4));

    const int warp_m = (w >> 2) * 32;
    const int warp_n = (w & 3) * 32;

    float acc[2][4][4];
#pragma unroll
    for (int mg = 0; mg < 2; mg++)
#pragma unroll
        for (int ng = 0; ng < 4; ng++)
#pragma unroll
            for (int k = 0; k < 4; k++) acc[mg][ng][k] = 0.f;

    // prefetch iter 0 (bf16: uint4 = 8 elements)
    uint4 xa_h, xa_l, wb_h0, wb_l0, wb_h1, wb_l1;
    {
        const size_t ao = (size_t)(bm + arow) * INF + achunk * 8;
        xa_h = *(const uint4*)(g_X1 + ao);
        xa_l = *(const uint4*)(g_X2 + ao);
        const size_t bo0 = (size_t)(bn + brow0) * INF + bchunk * 8;
        const size_t bo1 = (size_t)(bn + brow1) * INF + bchunk * 8;
        wb_h0 = *(const uint4*)(g_W1 + bo0);
        wb_l0 = *(const uint4*)(g_W2 + bo0);
        wb_h1 = *(const uint4*)(g_W1 + bo1);
        wb_l1 = *(const uint4*)(g_W2 + bo1);
    }

    for (int it = 0; it < INF / 32; it++) {
        const int buf = it & 1;
        *(uint4*)&Ah[buf][aoff]  = xa_h;
        *(uint4*)&Al[buf][aoff]  = xa_l;
        *(uint4*)&Bh[buf][boff0] = wb_h0;
        *(uint4*)&Bl[buf][boff0] = wb_l0;
        *(uint4*)&Bh[buf][boff1] = wb_h1;
        *(uint4*)&Bl[buf][boff1] = wb_l1;
        __syncthreads();

        if (it + 1 < INF / 32) {
            const int k0 = (it + 1) * 32;
            const size_t ao = (size_t)(bm + arow) * INF + k0 + achunk * 8;
            xa_h = *(const uint4*)(g_X1 + ao);
            xa_l = *(const uint4*)(g_X2 + ao);
            const size_t bo0 = (size_t)(bn + brow0) * INF + k0 + bchunk * 8;
            const size_t bo1 = (size_t)(bn + brow1) * INF + k0 + bchunk * 8;
            wb_h0 = *(const uint4*)(g_W1 + bo0);
            wb_l0 = *(const uint4*)(g_W2 + bo0);
            wb_h1 = *(const uint4*)(g_W1 + bo1);
            wb_l1 = *(const uint4*)(g_W2 + bo1);
        }

        const uint32_t aAh = smem_u32(&Ah[buf][0]);
        const uint32_t aAl = smem_u32(&Al[buf][0]);
        const uint32_t aBh = smem_u32(&Bh[buf][0]);
        const uint32_t aBl = smem_u32(&Bl[buf][0]);

        uint32_t bh[4][4], bl[4][4];
#pragma unroll
        for (int ng = 0; ng < 4; ng++) {
            const int row = warp_n + ng * 8 + (L & 7);
            const int ch  = L >> 3;
            const uint32_t off = (uint32_t)(row * 64 + ((ch ^ ((row >> 1) & 3)) << 4));
            ldmx4(bh[ng], aBh + off);
            ldmx4(bl[ng], aBl + off);
        }
        uint32_t ah[2][2][4], al[2][2][4];
#pragma unroll
        for (int mg = 0; mg < 2; mg++)
#pragma unroll
            for (int ks = 0; ks < 2; ks++) {
                const int mat = L >> 3;
                const int row = warp_m + mg * 16 + (L & 7) + (mat & 1) * 8;
                const int ch  = ks * 2 + (mat >> 1);
                const uint32_t off = (uint32_t)(row * 64 + ((ch ^ ((row >> 1) & 3)) << 4));
                ldmx4(ah[mg][ks], aAh + off);
                ldmx4(al[mg][ks], aAl + off);
            }

#pragma unroll
        for (int mg = 0; mg < 2; mg++)
#pragma unroll
            for (int ng = 0; ng < 4; ng++)
#pragma unroll
                for (int ks = 0; ks < 2; ks++) {
                    mma_bf16(acc[mg][ng], ah[mg][ks], bh[ng][2*ks], bh[ng][2*ks+1]);
                    mma_bf16(acc[mg][ng], ah[mg][ks], bl[ng][2*ks], bl[ng][2*ks+1]);
                    mma_bf16(acc[mg][ng], al[mg][ks], bh[ng][2*ks], bh[ng][2*ks+1]);
                }
        __syncthreads();
    }

#pragma unroll
    for (int mg = 0; mg < 2; mg++)
#pragma unroll
        for (int ng = 0; ng < 4; ng++) {
            const int row = bm + warp_m + mg * 16 + (L >> 2);
            const int col = bn + warp_n + ng * 8 + (L & 3) * 2;
            *(float2*)(g_h + (size_t)row * OF + col)       = make_float2(acc[mg][ng][0], acc[mg][ng][1]);
            *(float2*)(g_h + (size_t)(row + 8) * OF + col) = make_float2(acc[mg][ng][2], acc[mg][ng][3]);
        }
}

// ---------------- Kernel 2: per-(node,head) exp coefficients ----------------
__global__ void coef_kernel(const float* __restrict__ a_src,
                            const float* __restrict__ a_dst) {
    int idx = blockIdx.x * blockDim.x + threadIdx.x;
    int h = idx / NN;
    int n = idx % NN;
    const float4* hv = (const float4*)(g_h + (size_t)n * OF + h * HD);
    const float4* as = (const float4*)(a_src + h * HD);
    const float4* ad = (const float4*)(a_dst + h * HD);
    float s = 0.f, t = 0.f;
#pragma unroll
    for (int k = 0; k < 16; k++) {
        float4 hh = hv[k], va = as[k], vd = ad[k];
        s += hh.x * va.x + hh.y * va.y + hh.z * va.z + hh.w * va.w;
        t += hh.x * vd.x + hh.y * vd.y + hh.z * vd.z + hh.w * vd.w;
    }
    g_P[idx] = __expf(s);
    g_p[idx] = __expf(0.2f * s);
    g_Q[idx] = __expf(t);
    g_q[idx] = __expf(0.2f * t);
}

// ---------------- Kernel 3: adjacency (+diag) bitmask ----------------
__global__ __launch_bounds__(256) void mask_kernel(const int* __restrict__ adj) {
    const int gw = (blockIdx.x * blockDim.x + threadIdx.x) >> 5;
    const int L  = threadIdx.x & 31;
    const int i  = gw / (NN / 128);
    const int sp = gw % (NN / 128);
    const int c0 = sp * 128 + L * 4;
    const int4 v = *(const int4*)(adj + (size_t)i * NN + c0);
    unsigned nib = ((v.x != 0 || c0     == i) ? 1u : 0u)
                 | ((v.y != 0 || c0 + 1 == i) ? 2u : 0u)
                 | ((v.z != 0 || c0 + 2 == i) ? 4u : 0u)
                 | ((v.w != 0 || c0 + 3 == i) ? 8u : 0u);
    unsigned val = nib << ((L & 7) * 4);
    val |= __shfl_xor_sync(0xffffffffu, val, 1);
    val |= __shfl_xor_sync(0xffffffffu, val, 2);
    val |= __shfl_xor_sync(0xffffffffu, val, 4);
    if ((L & 7) == 0) g_mask[i * MW + sp * 4 + (L >> 3)] = val;
}

// ---------------- Kernel 3b: transpose + bf16 hi/lo split of h ----------------
__global__ __launch_bounds__(256) void hsplit_kernel() {
    __shared__ float tl[32][65];
    const int h  = blockIdx.y;
    const int n0 = blockIdx.x * 32;
    const int t  = threadIdx.x;
    {
        int r  = t >> 3;
        int c8 = (t & 7) * 8;
        const float* src = g_h + (size_t)(n0 + r) * OF + h * HD + c8;
        float4 v0 = *(const float4*)src;
        float4 v1 = *(const float4*)(src + 4);
        tl[r][c8+0] = v0.x; tl[r][c8+1] = v0.y; tl[r][c8+2] = v0.z; tl[r][c8+3] = v0.w;
        tl[r][c8+4] = v1.x; tl[r][c8+5] = v1.y; tl[r][c8+6] = v1.z; tl[r][c8+7] = v1.w;
    }
    __syncthreads();
    const int d  = t >> 2;
    const int ns = (t & 3) * 8;
    uint32_t hi[4], lo[4];
#pragma unroll
    for (int k = 0; k < 4; k++) {
        float va = tl[ns + 2*k][d];
        float vb = tl[ns + 2*k + 1][d];
        split2(va, vb, hi[k], lo[k]);
    }
    size_t o = (size_t)(h * HD + d) * NN + n0 + ns;
    *(uint4*)(g_hT1 + o) = make_uint4(hi[0], hi[1], hi[2], hi[3]);
    *(uint4*)(g_hT2 + o) = make_uint4(lo[0], lo[1], lo[2], lo[3]);
}

// ---------------- Kernel 4: HMMA masked softmax-aggregate ----------------
__global__ __launch_bounds__(256) void attn_kernel(float* __restrict__ out) {
    __shared__ __align__(16) unsigned char Bsm[2][2][HD * 64];
    __shared__ __align__(8)  float2 QQ[2][KT];

    const int tid  = threadIdx.x;
    const int w    = tid >> 5;
    const int L    = tid & 31;
    const int head = blockIdx.y;
    const int i0   = blockIdx.x * MT;

    const int sd   = tid >> 2;
    const int sseg = tid & 3;
    const __nv_bfloat16* h1p = g_hT1 + (size_t)(head * HD + sd) * NN;
    const __nv_bfloat16* h2p = g_hT2 + (size_t)(head * HD + sd) * NN;
    const uint32_t soff = (uint32_t)(sd * 64 + ((sseg ^ ((sd >> 1) & 3)) << 4));

    const int r  = L >> 2;
    const int cb = (L & 3) * 2;
    const int irow0 = i0 + w * 16 + r;
    const int irow1 = irow0 + 8;
    const float P0 = g_P[head * NN + irow0];
    const float p0 = g_p[head * NN + irow0];
    const float P1 = g_P[head * NN + irow1];
    const float p1 = g_p[head * NN + irow1];
    const unsigned* mrow0 = g_mask + (size_t)irow0 * MW;
    const unsigned* mrow1 = g_mask + (size_t)irow1 * MW;

    const uint32_t b1base = smem_u32(&Bsm[0][0][0]);

    float acc[8][4];
#pragma unroll
    for (int n = 0; n < 8; n++)
#pragma unroll
        for (int k = 0; k < 4; k++) acc[n][k] = 0.f;
    float z0 = 0.f, z1 = 0.f;

    uint4 nb1 = *(const uint4*)(h1p + sseg * 8);
    uint4 nb2 = *(const uint4*)(h2p + sseg * 8);
    unsigned nm0 = mrow0[0];
    unsigned nm1 = mrow1[0];
    float nQ = 0.f, nq = 0.f;
    if (tid < KT) {
        nQ = g_Q[head * NN + tid];
        nq = g_q[head * NN + tid];
    }

    for (int t = 0; t < NTILES; t++) {
        const int buf = t & 1;
        *(uint4*)&Bsm[buf][0][soff] = nb1;
        *(uint4*)&Bsm[buf][1][soff] = nb2;
        if (tid < KT) QQ[buf][tid] = make_float2(nQ, nq);
        const unsigned mw0 = nm0;
        const unsigned mw1 = nm1;
        __syncthreads();

        if (t + 1 < NTILES) {
            const int j0 = (t + 1) * KT;
            nb1 = *(const uint4*)(h1p + j0 + sseg * 8);
            nb2 = *(const uint4*)(h2p + j0 + sseg * 8);
            nm0 = mrow0[t + 1];
            nm1 = mrow1[t + 1];
            if (tid < KT) {
                nQ = g_Q[head * NN + j0 + tid];
                nq = g_q[head * NN + j0 + tid];
            }
        }

        uint32_t A1[2][4], A2[2][4];
#pragma unroll
        for (int ks = 0; ks < 2; ks++) {
            const int jb = cb + ks * 16;
            float2 q0 = QQ[buf][jb];
            float2 q1 = QQ[buf][jb + 1];
            float2 q2 = QQ[buf][jb + 8];
            float2 q3 = QQ[buf][jb + 9];
            float w00 = fmaxf(P0 * q0.x, p0 * q0.y); w00 = ((mw0 >> jb)       & 1u) ? w00 : 0.f;
            float w01 = fmaxf(P0 * q1.x, p0 * q1.y); w01 = ((mw0 >> (jb + 1)) & 1u) ? w01 : 0.f;
            float w02 = fmaxf(P0 * q2.x, p0 * q2.y); w02 = ((mw0 >> (jb + 8)) & 1u) ? w02 : 0.f;
            float w03 = fmaxf(P0 * q3.x, p0 * q3.y); w03 = ((mw0 >> (jb + 9)) & 1u) ? w03 : 0.f;
            float w10 = fmaxf(P1 * q0.x, p1 * q0.y); w10 = ((mw1 >> jb)       & 1u) ? w10 : 0.f;
            float w11 = fmaxf(P1 * q1.x, p1 * q1.y); w11 = ((mw1 >> (jb + 1)) & 1u) ? w11 : 0.f;
            float w12 = fmaxf(P1 * q2.x, p1 * q2.y); w12 = ((mw1 >> (jb + 8)) & 1u) ? w12 : 0.f;
            float w13 = fmaxf(P1 * q3.x, p1 * q3.y); w13 = ((mw1 >> (jb + 9)) & 1u) ? w13 : 0.f;
            z0 += (w00 + w01) + (w02 + w03);
            z1 += (w10 + w11) + (w12 + w13);
            split2(w00, w01, A1[ks][0], A2[ks][0]);
            split2(w10, w11, A1[ks][1], A2[ks][1]);
            split2(w02, w03, A1[ks][2], A2[ks][2]);
            split2(w12, w13, A1[ks][3], A2[ks][3]);
        }

        const uint32_t bufofs = (uint32_t)buf * (2 * HD * 64);
        const int ld_d = (L & 7);
        const int ld_m = (L >> 3);
#pragma unroll
        for (int nt = 0; nt < 8; nt++) {
            const int d = nt * 8 + ld_d;
            const uint32_t addr1 = b1base + bufofs + (uint32_t)(d * 64 + ((ld_m ^ ((d >> 1) & 3)) << 4));
            const uint32_t addr2 = addr1 + (uint32_t)(HD * 64);
            uint32_t B1[4], B2[4];
            ldmx4(B1, addr1);
            ldmx4(B2, addr2);
            mma_bf16(acc[nt], A1[0], B1[0], B1[1]);
            mma_bf16(acc[nt], A1[1], B1[2], B1[3]);
            mma_bf16(acc[nt], A1[0], B2[0], B2[1]);
            mma_bf16(acc[nt], A1[1], B2[2], B2[3]);
            mma_bf16(acc[nt], A2[0], B1[0], B1[1]);
            mma_bf16(acc[nt], A2[1], B1[2], B1[3]);
        }
    }

    z0 += __shfl_xor_sync(0xffffffffu, z0, 1);
    z0 += __shfl_xor_sync(0xffffffffu, z0, 2);
    z1 += __shfl_xor_sync(0xffffffffu, z1, 1);
    z1 += __shfl_xor_sync(0xffffffffu, z1, 2);
    const float iz0 = 1.0f / z0;
    const float iz1 = 1.0f / z1;

    float* o0 = out + (size_t)irow0 * OF + head * HD + cb;
    float* o1 = out + (size_t)irow1 * OF + head * HD + cb;
#pragma unroll
    for (int nt = 0; nt < 8; nt++) {
        *(float2*)(o0 + nt * 8) = make_float2(acc[nt][0] * iz0, acc[nt][1] * iz0);
        *(float2*)(o1 + nt * 8) = make_float2(acc[nt][2] * iz1, acc[nt][3] * iz1);
    }
}

// ---------------- launch ----------------
extern "C" void kernel_launch(void* const* d_in, const int* in_sizes, int n_in,
                              void* d_out, int out_size) {
    const float* x     = (const float*)d_in[0];
    const int*   adj   = (const int*)d_in[1];
    const float* W     = (const float*)d_in[2];
    const float* a_src = (const float*)d_in[3];
    const float* a_dst = (const float*)d_in[4];
    float* out = (float*)d_out;

    __nv_bfloat16 *x1, *x2, *w1, *w2;
    cudaGetSymbolAddress((void**)&x1, g_X1);
    cudaGetSymbolAddress((void**)&x2, g_X2);
    cudaGetSymbolAddress((void**)&w1, g_W1);
    cudaGetSymbolAddress((void**)&w2, g_W2);

    fsplit_kernel<<<(NN * INF) / 1024, 256>>>(x, x1, x2);
    fsplit_kernel<<<(OF * INF) / 1024, 256>>>(W, w1, w2);
    mask_kernel<<<(NN * (NN / 128) * 32) / 256, 256>>>(adj);
    gemm_kernel<<<dim3(NN / 64, OF / 128), 256>>>();
    coef_kernel<<<(NH * NN) / 256, 256>>>(a_src, a_dst);
    hsplit_kernel<<<dim3(NN / 32, NH), 256>>>();
    attn_kernel<<<dim3(NN / MT, NH), 256>>>(out);
}

// round 7
// speedup vs baseline: 1.6695x; 1.0874x over previous
#include <cuda_runtime.h>
#include <cuda_bf16.h>
#include <cstdint>

#define NN   3072
#define INF  512
#define NH   8
#define HD   64
#define OF   512   // NH*HD
#define MW   96    // mask words per row
#define KT   32    // attn j tile
#define MT   128   // attn i tile per CTA
#define NTILES (NN / KT)
#define BROW 36    // B smem row pitch in floats (144B, conflict-free)

// ---------------- scratch ----------------
__device__ float         g_h[NN * OF];
__device__ float         g_P[NH * NN];
__device__ float         g_p[NH * NN];
__device__ float         g_Q[NH * NN];
__device__ float         g_q[NH * NN];
__device__ unsigned      g_mask[NN * MW];
__device__ float         g_hTf[NH * HD * NN];      // [h][d][n], tf32-rounded fp32
__device__ __nv_bfloat16 g_X1[NN * INF];           // X hi split
__device__ __nv_bfloat16 g_X2[NN * INF];           // X lo
__device__ __nv_bfloat16 g_W1[OF * INF];           // W hi
__device__ __nv_bfloat16 g_W2[OF * INF];           // W lo

__device__ __forceinline__ uint32_t smem_u32(const void* p) {
    uint32_t a;
    asm("{ .reg .u64 t; cvta.to.shared.u64 t, %1; cvt.u32.u64 %0, t; }" : "=r"(a) : "l"(p));
    return a;
}

__device__ __forceinline__ void mma_bf16(float* c, const uint32_t* a, uint32_t b0, uint32_t b1) {
    asm volatile(
        "mma.sync.aligned.m16n8k16.row.col.f32.bf16.bf16.f32 "
        "{%0,%1,%2,%3}, {%4,%5,%6,%7}, {%8,%9}, {%0,%1,%2,%3};"
        : "+f"(c[0]), "+f"(c[1]), "+f"(c[2]), "+f"(c[3])
        : "r"(a[0]), "r"(a[1]), "r"(a[2]), "r"(a[3]), "r"(b0), "r"(b1));
}

__device__ __forceinline__ void mma_tf32(float* c, const uint32_t* a, uint32_t b0, uint32_t b1) {
    asm volatile(
        "mma.sync.aligned.m16n8k8.row.col.f32.tf32.tf32.f32 "
        "{%0,%1,%2,%3}, {%4,%5,%6,%7}, {%8,%9}, {%0,%1,%2,%3};"
        : "+f"(c[0]), "+f"(c[1]), "+f"(c[2]), "+f"(c[3])
        : "r"(a[0]), "r"(a[1]), "r"(a[2]), "r"(a[3]), "r"(b0), "r"(b1));
}

__device__ __forceinline__ void ldmx4(uint32_t* r, uint32_t addr) {
    asm volatile("ldmatrix.sync.aligned.m8n8.x4.shared.b16 {%0,%1,%2,%3}, [%4];"
                 : "=r"(r[0]), "=r"(r[1]), "=r"(r[2]), "=r"(r[3]) : "r"(addr));
}

__device__ __forceinline__ void split2(float w0, float w1, uint32_t& hi, uint32_t& lo) {
    uint32_t h;
    asm("cvt.rn.bf16x2.f32 %0, %1, %2;" : "=r"(h) : "f"(w1), "f"(w0));
    float r0 = w0 - __uint_as_float(h << 16);
    float r1 = w1 - __uint_as_float(h & 0xffff0000u);
    uint32_t l;
    asm("cvt.rn.bf16x2.f32 %0, %1, %2;" : "=r"(l) : "f"(r1), "f"(r0));
    hi = h; lo = l;
}

__device__ __forceinline__ uint32_t tf32r(float v) {
    uint32_t d;
    asm("cvt.rna.tf32.f32 %0, %1;" : "=r"(d) : "f"(v));
    return d;
}

// ---------------- Kernel 0: fp32 -> bf16 hi/lo split ----------------
__global__ __launch_bounds__(256) void fsplit_kernel(const float* __restrict__ src,
                                                     __nv_bfloat16* __restrict__ dhi,
                                                     __nv_bfloat16* __restrict__ dlo) {
    const int idx = (blockIdx.x * blockDim.x + threadIdx.x) * 4;
    float4 v = *(const float4*)(src + idx);
    uint32_t h0, h1, l0, l1;
    split2(v.x, v.y, h0, l0);
    split2(v.z, v.w, h1, l1);
    *(uint2*)(dhi + idx) = make_uint2(h0, h1);
    *(uint2*)(dlo + idx) = make_uint2(l0, l1);
}

// ---------------- Kernel 1: g_h = X @ W^T (bf16-split HMMA) ----------------
__global__ __launch_bounds__(256) void gemm_kernel() {
    __shared__ __align__(16) unsigned char Ah[2][64 * 64];
    __shared__ __align__(16) unsigned char Al[2][64 * 64];
    __shared__ __align__(16) unsigned char Bh[2][128 * 64];
    __shared__ __align__(16) unsigned char Bl[2][128 * 64];

    const int tid = threadIdx.x;
    const int w   = tid >> 5;
    const int L   = tid & 31;
    const int bm  = blockIdx.x * 64;
    const int bn  = blockIdx.y * 128;

    const int arow   = tid >> 2;
    const int achunk = tid & 3;
    const uint32_t aoff = (uint32_t)(arow * 64 + ((achunk ^ ((arow >> 1) & 3)) << 4));
    const int brow0  = tid >> 2;
    const int bchunk = tid & 3;
    const uint32_t boff0 = (uint32_t)(brow0 * 64 + ((bchunk ^ ((brow0 >> 1) & 3)) << 4));
    const int brow1  = 64 + brow0;
    const uint32_t boff1 = (uint32_t)(brow1 * 64 + ((bchunk ^ ((brow1 >> 1) & 3)) << 4));

    const int warp_m = (w >> 2) * 32;
    const int warp_n = (w & 3) * 32;

    float acc[2][4][4];
#pragma unroll
    for (int mg = 0; mg < 2; mg++)
#pragma unroll
        for (int ng = 0; ng < 4; ng++)
#pragma unroll
            for (int k = 0; k < 4; k++) acc[mg][ng][k] = 0.f;

    uint4 xa_h, xa_l, wb_h0, wb_l0, wb_h1, wb_l1;
    {
        const size_t ao = (size_t)(bm + arow) * INF + achunk * 8;
        xa_h = *(const uint4*)(g_X1 + ao);
        xa_l = *(const uint4*)(g_X2 + ao);
        const size_t bo0 = (size_t)(bn + brow0) * INF + bchunk * 8;
        const size_t bo1 = (size_t)(bn + brow1) * INF + bchunk * 8;
        wb_h0 = *(const uint4*)(g_W1 + bo0);
        wb_l0 = *(const uint4*)(g_W2 + bo0);
        wb_h1 = *(const uint4*)(g_W1 + bo1);
        wb_l1 = *(const uint4*)(g_W2 + bo1);
    }

    for (int it = 0; it < INF / 32; it++) {
        const int buf = it & 1;
        *(uint4*)&Ah[buf][aoff]  = xa_h;
        *(uint4*)&Al[buf][aoff]  = xa_l;
        *(uint4*)&Bh[buf][boff0] = wb_h0;
        *(uint4*)&Bl[buf][boff0] = wb_l0;
        *(uint4*)&Bh[buf][boff1] = wb_h1;
        *(uint4*)&Bl[buf][boff1] = wb_l1;
        __syncthreads();

        if (it + 1 < INF / 32) {
            const int k0 = (it + 1) * 32;
            const size_t ao = (size_t)(bm + arow) * INF + k0 + achunk * 8;
            xa_h = *(const uint4*)(g_X1 + ao);
            xa_l = *(const uint4*)(g_X2 + ao);
            const size_t bo0 = (size_t)(bn + brow0) * INF + k0 + bchunk * 8;
            const size_t bo1 = (size_t)(bn + brow1) * INF + k0 + bchunk * 8;
            wb_h0 = *(const uint4*)(g_W1 + bo0);
            wb_l0 = *(const uint4*)(g_W2 + bo0);
            wb_h1 = *(const uint4*)(g_W1 + bo1);
            wb_l1 = *(const uint4*)(g_W2 + bo1);
        }

        const uint32_t aAh = smem_u32(&Ah[buf][0]);
        const uint32_t aAl = smem_u32(&Al[buf][0]);
        const uint32_t aBh = smem_u32(&Bh[buf][0]);
        const uint32_t aBl = smem_u32(&Bl[buf][0]);

        uint32_t bh[4][4], bl[4][4];
#pragma unroll
        for (int ng = 0; ng < 4; ng++) {
            const int row = warp_n + ng * 8 + (L & 7);
            const int ch  = L >> 3;
            const uint32_t off = (uint32_t)(row * 64 + ((ch ^ ((row >> 1) & 3)) << 4));
            ldmx4(bh[ng], aBh + off);
            ldmx4(bl[ng], aBl + off);
        }
        uint32_t ah[2][2][4], al[2][2][4];
#pragma unroll
        for (int mg = 0; mg < 2; mg++)
#pragma unroll
            for (int ks = 0; ks < 2; ks++) {
                const int mat = L >> 3;
                const int row = warp_m + mg * 16 + (L & 7) + (mat & 1) * 8;
                const int ch  = ks * 2 + (mat >> 1);
                const uint32_t off = (uint32_t)(row * 64 + ((ch ^ ((row >> 1) & 3)) << 4));
                ldmx4(ah[mg][ks], aAh + off);
                ldmx4(al[mg][ks], aAl + off);
            }

#pragma unroll
        for (int mg = 0; mg < 2; mg++)
#pragma unroll
            for (int ng = 0; ng < 4; ng++)
#pragma unroll
                for (int ks = 0; ks < 2; ks++) {
                    mma_bf16(acc[mg][ng], ah[mg][ks], bh[ng][2*ks], bh[ng][2*ks+1]);
                    mma_bf16(acc[mg][ng], ah[mg][ks], bl[ng][2*ks], bl[ng][2*ks+1]);
                    mma_bf16(acc[mg][ng], al[mg][ks], bh[ng][2*ks], bh[ng][2*ks+1]);
                }
        __syncthreads();
    }

#pragma unroll
    for (int mg = 0; mg < 2; mg++)
#pragma unroll
        for (int ng = 0; ng < 4; ng++) {
            const int row = bm + warp_m + mg * 16 + (L >> 2);
            const int col = bn + warp_n + ng * 8 + (L & 3) * 2;
            *(float2*)(g_h + (size_t)row * OF + col)       = make_float2(acc[mg][ng][0], acc[mg][ng][1]);
            *(float2*)(g_h + (size_t)(row + 8) * OF + col) = make_float2(acc[mg][ng][2], acc[mg][ng][3]);
        }
}

// ---------------- Kernel 2: per-(node,head) exp coefficients ----------------
__global__ void coef_kernel(const float* __restrict__ a_src,
                            const float* __restrict__ a_dst) {
    int idx = blockIdx.x * blockDim.x + threadIdx.x;
    int h = idx / NN;
    int n = idx % NN;
    const float4* hv = (const float4*)(g_h + (size_t)n * OF + h * HD);
    const float4* as = (const float4*)(a_src + h * HD);
    const float4* ad = (const float4*)(a_dst + h * HD);
    float s = 0.f, t = 0.f;
#pragma unroll
    for (int k = 0; k < 16; k++) {
        float4 hh = hv[k], va = as[k], vd = ad[k];
        s += hh.x * va.x + hh.y * va.y + hh.z * va.z + hh.w * va.w;
        t += hh.x * vd.x + hh.y * vd.y + hh.z * vd.z + hh.w * vd.w;
    }
    g_P[idx] = __expf(s);
    g_p[idx] = __expf(0.2f * s);
    g_Q[idx] = __expf(t);
    g_q[idx] = __expf(0.2f * t);
}

// ---------------- Kernel 3: adjacency (+diag) bitmask ----------------
__global__ __launch_bounds__(256) void mask_kernel(const int* __restrict__ adj) {
    const int gw = (blockIdx.x * blockDim.x + threadIdx.x) >> 5;
    const int L  = threadIdx.x & 31;
    const int i  = gw / (NN / 128);
    const int sp = gw % (NN / 128);
    const int c0 = sp * 128 + L * 4;
    const int4 v = *(const int4*)(adj + (size_t)i * NN + c0);
    unsigned nib = ((v.x != 0 || c0     == i) ? 1u : 0u)
                 | ((v.y != 0 || c0 + 1 == i) ? 2u : 0u)
                 | ((v.z != 0 || c0 + 2 == i) ? 4u : 0u)
                 | ((v.w != 0 || c0 + 3 == i) ? 8u : 0u);
    unsigned val = nib << ((L & 7) * 4);
    val |= __shfl_xor_sync(0xffffffffu, val, 1);
    val |= __shfl_xor_sync(0xffffffffu, val, 2);
    val |= __shfl_xor_sync(0xffffffffu, val, 4);
    if ((L & 7) == 0) g_mask[i * MW + sp * 4 + (L >> 3)] = val;
}

// ---------------- Kernel 3b: transpose h + tf32-round ----------------
__global__ __launch_bounds__(256) void htrans_kernel() {
    __shared__ float tl[32][65];
    const int h  = blockIdx.y;
    const int n0 = blockIdx.x * 32;
    const int t  = threadIdx.x;
    {
        int r  = t >> 3;
        int c8 = (t & 7) * 8;
        const float* src = g_h + (size_t)(n0 + r) * OF + h * HD + c8;
        float4 v0 = *(const float4*)src;
        float4 v1 = *(const float4*)(src + 4);
        tl[r][c8+0] = v0.x; tl[r][c8+1] = v0.y; tl[r][c8+2] = v0.z; tl[r][c8+3] = v0.w;
        tl[r][c8+4] = v1.x; tl[r][c8+5] = v1.y; tl[r][c8+6] = v1.z; tl[r][c8+7] = v1.w;
    }
    __syncthreads();
    const int d  = t >> 2;
    const int ns = (t & 3) * 8;
    uint32_t o0[4], o1[4];
#pragma unroll
    for (int k = 0; k < 4; k++) {
        o0[k] = tf32r(tl[ns + k][d]);
        o1[k] = tf32r(tl[ns + 4 + k][d]);
    }
    size_t o = (size_t)(h * HD + d) * NN + n0 + ns;
    *(uint4*)(g_hTf + o)     = make_uint4(o0[0], o0[1], o0[2], o0[3]);
    *(uint4*)(g_hTf + o + 4) = make_uint4(o1[0], o1[1], o1[2], o1[3]);
}

// ---------------- Kernel 4: tf32 MMA masked softmax-aggregate ----------------
// CTA = 128 i x 1 head, 8 warps, warp = 16 i x 64 d. A (tf32 w) generated in
// fragment registers; Z summed from the SAME tf32-rounded w (exact weighted avg).
// B smem: rows d (pitch 36 floats = 144B, conflict-free), j permuted so one
// LDS.128 yields (k,k+4) for two consecutive k-steps: slot(j) = (j&3)*8 + (j>>2).
__global__ __launch_bounds__(256) void attn_kernel(float* __restrict__ out) {
    __shared__ __align__(16) float Bsm[2][HD * BROW];  // 2 x 9216B
    __shared__ __align__(8)  float2 QQ[2][KT];

    const int tid  = threadIdx.x;
    const int w    = tid >> 5;
    const int L    = tid & 31;
    const int head = blockIdx.y;
    const int i0   = blockIdx.x * MT;

    // staging role: row sd (d), chunk c4 (8 j's)
    const int sd = tid >> 2;
    const int c4 = tid & 3;
    const float* hp = g_hTf + (size_t)(head * HD + sd) * NN;

    // fragment role
    const int gr = L >> 2;          // fragment row 0..7
    const int c  = L & 3;           // fragment k-col
    const int irow0 = i0 + w * 16 + gr;
    const int irow1 = irow0 + 8;
    const float P0 = g_P[head * NN + irow0];
    const float p0 = g_p[head * NN + irow0];
    const float P1 = g_P[head * NN + irow1];
    const float p1 = g_p[head * NN + irow1];
    const unsigned* mrow0 = g_mask + (size_t)irow0 * MW;
    const unsigned* mrow1 = g_mask + (size_t)irow1 * MW;

    float acc[8][4];
#pragma unroll
    for (int n = 0; n < 8; n++)
#pragma unroll
        for (int k = 0; k < 4; k++) acc[n][k] = 0.f;
    float z0 = 0.f, z1 = 0.f;

    // prefetch tile 0
    float4 nv0 = *(const float4*)(hp + c4 * 8);
    float4 nv1 = *(const float4*)(hp + c4 * 8 + 4);
    unsigned nm0 = mrow0[0];
    unsigned nm1 = mrow1[0];
    float nQ = 0.f, nq = 0.f;
    if (tid < KT) {
        nQ = g_Q[head * NN + tid];
        nq = g_q[head * NN + tid];
    }

    for (int t = 0; t < NTILES; t++) {
        const int buf = t & 1;
        // store staged B with slot permutation: j = c4*8 + m -> slot (m&3)*8 + 2*c4 + (m>>2)
        {
            float* base = &Bsm[buf][sd * BROW];
            const int s0 = 2 * c4;
            base[0 * 8 + s0]     = nv0.x;
            base[1 * 8 + s0]     = nv0.y;
            base[2 * 8 + s0]     = nv0.z;
            base[3 * 8 + s0]     = nv0.w;
            base[0 * 8 + s0 + 1] = nv1.x;
            base[1 * 8 + s0 + 1] = nv1.y;
            base[2 * 8 + s0 + 1] = nv1.z;
            base[3 * 8 + s0 + 1] = nv1.w;
        }
        if (tid < KT) QQ[buf][tid] = make_float2(nQ, nq);
        const unsigned mw0 = nm0;
        const unsigned mw1 = nm1;
        __syncthreads();

        // prefetch next tile
        if (t + 1 < NTILES) {
            const int j0 = (t + 1) * KT;
            nv0 = *(const float4*)(hp + j0 + c4 * 8);
            nv1 = *(const float4*)(hp + j0 + c4 * 8 + 4);
            nm0 = mrow0[t + 1];
            nm1 = mrow1[t + 1];
            if (tid < KT) {
                nQ = g_Q[head * NN + j0 + tid];
                nq = g_q[head * NN + j0 + tid];
            }
        }

        // ---- A fragments (tf32 w), Z from same rounded values ----
        uint32_t A[4][4];
#pragma unroll
        for (int s = 0; s < 4; s++) {
            const int ja = 8 * s + c;
            const int jb = ja + 4;
            float2 qa = QQ[buf][ja];
            float2 qb = QQ[buf][jb];
            float wa0 = fmaxf(P0 * qa.x, p0 * qa.y); wa0 = ((mw0 >> ja) & 1u) ? wa0 : 0.f;
            float wa1 = fmaxf(P1 * qa.x, p1 * qa.y); wa1 = ((mw1 >> ja) & 1u) ? wa1 : 0.f;
            float wb0 = fmaxf(P0 * qb.x, p0 * qb.y); wb0 = ((mw0 >> jb) & 1u) ? wb0 : 0.f;
            float wb1 = fmaxf(P1 * qb.x, p1 * qb.y); wb1 = ((mw1 >> jb) & 1u) ? wb1 : 0.f;
            A[s][0] = tf32r(wa0);
            A[s][1] = tf32r(wa1);
            A[s][2] = tf32r(wb0);
            A[s][3] = tf32r(wb1);
            z0 += __uint_as_float(A[s][0]) + __uint_as_float(A[s][2]);
            z1 += __uint_as_float(A[s][1]) + __uint_as_float(A[s][3]);
        }

        // ---- B loads (LDS.128, conflict-free) + MMA ----
#pragma unroll
        for (int nt = 0; nt < 8; nt++) {
            const float4* bp = (const float4*)(&Bsm[buf][(nt * 8 + gr) * BROW + c * 8]);
            float4 v0 = bp[0];   // k-steps 0,1
            float4 v1 = bp[1];   // k-steps 2,3
            mma_tf32(acc[nt], A[0], __float_as_uint(v0.x), __float_as_uint(v0.y));
            mma_tf32(acc[nt], A[1], __float_as_uint(v0.z), __float_as_uint(v0.w));
            mma_tf32(acc[nt], A[2], __float_as_uint(v1.x), __float_as_uint(v1.y));
            mma_tf32(acc[nt], A[3], __float_as_uint(v1.z), __float_as_uint(v1.w));
        }
        __syncthreads();
    }

    z0 += __shfl_xor_sync(0xffffffffu, z0, 1);
    z0 += __shfl_xor_sync(0xffffffffu, z0, 2);
    z1 += __shfl_xor_sync(0xffffffffu, z1, 1);
    z1 += __shfl_xor_sync(0xffffffffu, z1, 2);
    const float iz0 = 1.0f / z0;   // diagonal always masked-in -> Z > 0
    const float iz1 = 1.0f / z1;

    const int cb = c * 2;
    float* o0 = out + (size_t)irow0 * OF + head * HD + cb;
    float* o1 = out + (size_t)irow1 * OF + head * HD + cb;
#pragma unroll
    for (int nt = 0; nt < 8; nt++) {
        *(float2*)(o0 + nt * 8) = make_float2(acc[nt][0] * iz0, acc[nt][1] * iz0);
        *(float2*)(o1 + nt * 8) = make_float2(acc[nt][2] * iz1, acc[nt][3] * iz1);
    }
}

// ---------------- launch ----------------
extern "C" void kernel_launch(void* const* d_in, const int* in_sizes, int n_in,
                              void* d_out, int out_size) {
    const float* x     = (const float*)d_in[0];
    const int*   adj   = (const int*)d_in[1];
    const float* W     = (const float*)d_in[2];
    const float* a_src = (const float*)d_in[3];
    const float* a_dst = (const float*)d_in[4];
    float* out = (float*)d_out;

    __nv_bfloat16 *x1, *x2, *w1, *w2;
    cudaGetSymbolAddress((void**)&x1, g_X1);
    cudaGetSymbolAddress((void**)&x2, g_X2);
    cudaGetSymbolAddress((void**)&w1, g_W1);
    cudaGetSymbolAddress((void**)&w2, g_W2);

    fsplit_kernel<<<(NN * INF) / 1024, 256>>>(x, x1, x2);
    fsplit_kernel<<<(OF * INF) / 1024, 256>>>(W, w1, w2);
    mask_kernel<<<(NN * (NN / 128) * 32) / 256, 256>>>(adj);
    gemm_kernel<<<dim3(NN / 64, OF / 128), 256>>>();
    coef_kernel<<<(NH * NN) / 256, 256>>>(a_src, a_dst);
    htrans_kernel<<<dim3(NN / 32, NH), 256>>>();
    attn_kernel<<<dim3(NN / MT, NH), 256>>>(out);
}

// round 8
// speedup vs baseline: 1.7267x; 1.0342x over previous
#include <cuda_runtime.h>
#include <cuda_bf16.h>
#include <cstdint>

#define NN   3072
#define INF  512
#define NH   8
#define HD   64
#define OF   512   // NH*HD
#define MW   96    // mask words per row
#define KT   32    // attn j tile
#define MT   128   // attn i tile per CTA
#define NTILES (NN / KT)
#define BROW 36    // B smem row pitch in floats (144B, conflict-free)

// ---------------- scratch ----------------
__device__ float         g_h[NN * OF];
__device__ float         g_P[NH * NN];
__device__ float         g_p[NH * NN];
__device__ float         g_Q[NH * NN];
__device__ float         g_q[NH * NN];
__device__ unsigned      g_mask[NN * MW];
__device__ float         g_hTf[NH * HD * NN];      // [h][d][n], tf32-rounded fp32
__device__ __nv_bfloat16 g_X1[NN * INF];
__device__ __nv_bfloat16 g_X2[NN * INF];
__device__ __nv_bfloat16 g_W1[OF * INF];
__device__ __nv_bfloat16 g_W2[OF * INF];

__device__ __forceinline__ uint32_t smem_u32(const void* p) {
    uint32_t a;
    asm("{ .reg .u64 t; cvta.to.shared.u64 t, %1; cvt.u32.u64 %0, t; }" : "=r"(a) : "l"(p));
    return a;
}

__device__ __forceinline__ void mma_bf16(float* c, const uint32_t* a, uint32_t b0, uint32_t b1) {
    asm volatile(
        "mma.sync.aligned.m16n8k16.row.col.f32.bf16.bf16.f32 "
        "{%0,%1,%2,%3}, {%4,%5,%6,%7}, {%8,%9}, {%0,%1,%2,%3};"
        : "+f"(c[0]), "+f"(c[1]), "+f"(c[2]), "+f"(c[3])
        : "r"(a[0]), "r"(a[1]), "r"(a[2]), "r"(a[3]), "r"(b0), "r"(b1));
}

__device__ __forceinline__ void mma_tf32(float* c, const uint32_t* a, uint32_t b0, uint32_t b1) {
    asm volatile(
        "mma.sync.aligned.m16n8k8.row.col.f32.tf32.tf32.f32 "
        "{%0,%1,%2,%3}, {%4,%5,%6,%7}, {%8,%9}, {%0,%1,%2,%3};"
        : "+f"(c[0]), "+f"(c[1]), "+f"(c[2]), "+f"(c[3])
        : "r"(a[0]), "r"(a[1]), "r"(a[2]), "r"(a[3]), "r"(b0), "r"(b1));
}

__device__ __forceinline__ void ldmx4(uint32_t* r, uint32_t addr) {
    asm volatile("ldmatrix.sync.aligned.m8n8.x4.shared.b16 {%0,%1,%2,%3}, [%4];"
                 : "=r"(r[0]), "=r"(r[1]), "=r"(r[2]), "=r"(r[3]) : "r"(addr));
}

__device__ __forceinline__ void split2(float w0, float w1, uint32_t& hi, uint32_t& lo) {
    uint32_t h;
    asm("cvt.rn.bf16x2.f32 %0, %1, %2;" : "=r"(h) : "f"(w1), "f"(w0));
    float r0 = w0 - __uint_as_float(h << 16);
    float r1 = w1 - __uint_as_float(h & 0xffff0000u);
    uint32_t l;
    asm("cvt.rn.bf16x2.f32 %0, %1, %2;" : "=r"(l) : "f"(r1), "f"(r0));
    hi = h; lo = l;
}

__device__ __forceinline__ uint32_t tf32r(float v) {
    uint32_t d;
    asm("cvt.rna.tf32.f32 %0, %1;" : "=r"(d) : "f"(v));
    return d;
}

// ---------------- Kernel 0: fp32 -> bf16 hi/lo split ----------------
__global__ __launch_bounds__(256) void fsplit_kernel(const float* __restrict__ src,
                                                     __nv_bfloat16* __restrict__ dhi,
                                                     __nv_bfloat16* __restrict__ dlo) {
    const int idx = (blockIdx.x * blockDim.x + threadIdx.x) * 4;
    float4 v = *(const float4*)(src + idx);
    uint32_t h0, h1, l0, l1;
    split2(v.x, v.y, h0, l0);
    split2(v.z, v.w, h1, l1);
    *(uint2*)(dhi + idx) = make_uint2(h0, h1);
    *(uint2*)(dlo + idx) = make_uint2(l0, l1);
}

// ---------------- Kernel 1: g_h = X @ W^T (bf16-split HMMA) ----------------
__global__ __launch_bounds__(256, 2) void gemm_kernel() {
    __shared__ __align__(16) unsigned char Ah[2][64 * 64];
    __shared__ __align__(16) unsigned char Al[2][64 * 64];
    __shared__ __align__(16) unsigned char Bh[2][128 * 64];
    __shared__ __align__(16) unsigned char Bl[2][128 * 64];

    const int tid = threadIdx.x;
    const int w   = tid >> 5;
    const int L   = tid & 31;
    const int bm  = blockIdx.x * 64;
    const int bn  = blockIdx.y * 128;

    const int arow   = tid >> 2;
    const int achunk = tid & 3;
    const uint32_t aoff = (uint32_t)(arow * 64 + ((achunk ^ ((arow >> 1) & 3)) << 4));
    const int brow0  = tid >> 2;
    const int bchunk = tid & 3;
    const uint32_t boff0 = (uint32_t)(brow0 * 64 + ((bchunk ^ ((brow0 >> 1) & 3)) << 4));
    const int brow1  = 64 + brow0;
    const uint32_t boff1 = (uint32_t)(brow1 * 64 + ((bchunk ^ ((brow1 >> 1) & 3)) << 4));

    const int warp_m = (w >> 2) * 32;
    const int warp_n = (w & 3) * 32;

    float acc[2][4][4];
#pragma unroll
    for (int mg = 0; mg < 2; mg++)
#pragma unroll
        for (int ng = 0; ng < 4; ng++)
#pragma unroll
            for (int k = 0; k < 4; k++) acc[mg][ng][k] = 0.f;

    uint4 xa_h, xa_l, wb_h0, wb_l0, wb_h1, wb_l1;
    {
        const size_t ao = (size_t)(bm + arow) * INF + achunk * 8;
        xa_h = *(const uint4*)(g_X1 + ao);
        xa_l = *(const uint4*)(g_X2 + ao);
        const size_t bo0 = (size_t)(bn + brow0) * INF + bchunk * 8;
        const size_t bo1 = (size_t)(bn + brow1) * INF + bchunk * 8;
        wb_h0 = *(const uint4*)(g_W1 + bo0);
        wb_l0 = *(const uint4*)(g_W2 + bo0);
        wb_h1 = *(const uint4*)(g_W1 + bo1);
        wb_l1 = *(const uint4*)(g_W2 + bo1);
    }

    for (int it = 0; it < INF / 32; it++) {
        const int buf = it & 1;
        *(uint4*)&Ah[buf][aoff]  = xa_h;
        *(uint4*)&Al[buf][aoff]  = xa_l;
        *(uint4*)&Bh[buf][boff0] = wb_h0;
        *(uint4*)&Bl[buf][boff0] = wb_l0;
        *(uint4*)&Bh[buf][boff1] = wb_h1;
        *(uint4*)&Bl[buf][boff1] = wb_l1;
        __syncthreads();

        if (it + 1 < INF / 32) {
            const int k0 = (it + 1) * 32;
            const size_t ao = (size_t)(bm + arow) * INF + k0 + achunk * 8;
            xa_h = *(const uint4*)(g_X1 + ao);
            xa_l = *(const uint4*)(g_X2 + ao);
            const size_t bo0 = (size_t)(bn + brow0) * INF + k0 + bchunk * 8;
            const size_t bo1 = (size_t)(bn + brow1) * INF + k0 + bchunk * 8;
            wb_h0 = *(const uint4*)(g_W1 + bo0);
            wb_l0 = *(const uint4*)(g_W2 + bo0);
            wb_h1 = *(const uint4*)(g_W1 + bo1);
            wb_l1 = *(const uint4*)(g_W2 + bo1);
        }

        const uint32_t aAh = smem_u32(&Ah[buf][0]);
        const uint32_t aAl = smem_u32(&Al[buf][0]);
        const uint32_t aBh = smem_u32(&Bh[buf][0]);
        const uint32_t aBl = smem_u32(&Bl[buf][0]);

        uint32_t bh[4][4], bl[4][4];
#pragma unroll
        for (int ng = 0; ng < 4; ng++) {
            const int row = warp_n + ng * 8 + (L & 7);
            const int ch  = L >> 3;
            const uint32_t off = (uint32_t)(row * 64 + ((ch ^ ((row >> 1) & 3)) << 4));
            ldmx4(bh[ng], aBh + off);
            ldmx4(bl[ng], aBl + off);
        }
        uint32_t ah[2][2][4], al[2][2][4];
#pragma unroll
        for (int mg = 0; mg < 2; mg++)
#pragma unroll
            for (int ks = 0; ks < 2; ks++) {
                const int mat = L >> 3;
                const int row = warp_m + mg * 16 + (L & 7) + (mat & 1) * 8;
                const int ch  = ks * 2 + (mat >> 1);
                const uint32_t off = (uint32_t)(row * 64 + ((ch ^ ((row >> 1) & 3)) << 4));
                ldmx4(ah[mg][ks], aAh + off);
                ldmx4(al[mg][ks], aAl + off);
            }

#pragma unroll
        for (int mg = 0; mg < 2; mg++)
#pragma unroll
            for (int ng = 0; ng < 4; ng++)
#pragma unroll
                for (int ks = 0; ks < 2; ks++) {
                    mma_bf16(acc[mg][ng], ah[mg][ks], bh[ng][2*ks], bh[ng][2*ks+1]);
                    mma_bf16(acc[mg][ng], ah[mg][ks], bl[ng][2*ks], bl[ng][2*ks+1]);
                    mma_bf16(acc[mg][ng], al[mg][ks], bh[ng][2*ks], bh[ng][2*ks+1]);
                }
        __syncthreads();
    }

#pragma unroll
    for (int mg = 0; mg < 2; mg++)
#pragma unroll
        for (int ng = 0; ng < 4; ng++) {
            const int row = bm + warp_m + mg * 16 + (L >> 2);
            const int col = bn + warp_n + ng * 8 + (L & 3) * 2;
            *(float2*)(g_h + (size_t)row * OF + col)       = make_float2(acc[mg][ng][0], acc[mg][ng][1]);
            *(float2*)(g_h + (size_t)(row + 8) * OF + col) = make_float2(acc[mg][ng][2], acc[mg][ng][3]);
        }
}

// ---------------- Kernel 3: adjacency (+diag) bitmask, MLP=2 ----------------
// Warp = 256 cols of one row (two 128-col groups), lane loads two int4.
__global__ __launch_bounds__(256) void mask_kernel(const int* __restrict__ adj) {
    const int gw = (blockIdx.x * blockDim.x + threadIdx.x) >> 5;
    const int L  = threadIdx.x & 31;
    const int i  = gw / (NN / 256);
    const int sp = gw % (NN / 256);
    const int c0 = sp * 256 + L * 4;
    const int c1 = c0 + 128;
    const int4 v0 = *(const int4*)(adj + (size_t)i * NN + c0);
    const int4 v1 = *(const int4*)(adj + (size_t)i * NN + c1);
    unsigned nib0 = ((v0.x != 0 || c0     == i) ? 1u : 0u)
                  | ((v0.y != 0 || c0 + 1 == i) ? 2u : 0u)
                  | ((v0.z != 0 || c0 + 2 == i) ? 4u : 0u)
                  | ((v0.w != 0 || c0 + 3 == i) ? 8u : 0u);
    unsigned nib1 = ((v1.x != 0 || c1     == i) ? 1u : 0u)
                  | ((v1.y != 0 || c1 + 1 == i) ? 2u : 0u)
                  | ((v1.z != 0 || c1 + 2 == i) ? 4u : 0u)
                  | ((v1.w != 0 || c1 + 3 == i) ? 8u : 0u);
    unsigned a = nib0 << ((L & 7) * 4);
    unsigned b = nib1 << ((L & 7) * 4);
    a |= __shfl_xor_sync(0xffffffffu, a, 1);
    b |= __shfl_xor_sync(0xffffffffu, b, 1);
    a |= __shfl_xor_sync(0xffffffffu, a, 2);
    b |= __shfl_xor_sync(0xffffffffu, b, 2);
    a |= __shfl_xor_sync(0xffffffffu, a, 4);
    b |= __shfl_xor_sync(0xffffffffu, b, 4);
    if ((L & 7) == 0) {
        g_mask[i * MW + sp * 8 + (L >> 3)]     = a;
        g_mask[i * MW + sp * 8 + 4 + (L >> 3)] = b;
    }
}

// ---------------- Kernel 3b: fused transpose(tf32) + coef ----------------
// Block = 32 nodes x 1 head. Tile also yields the coef dot products.
__global__ __launch_bounds__(256) void htrans_kernel(const float* __restrict__ a_src,
                                                     const float* __restrict__ a_dst) {
    __shared__ float tl[32][65];
    const int h  = blockIdx.y;
    const int n0 = blockIdx.x * 32;
    const int t  = threadIdx.x;
    const int r  = t >> 3;
    const int c8 = (t & 7) * 8;
    {
        const float* src = g_h + (size_t)(n0 + r) * OF + h * HD + c8;
        float4 v0 = *(const float4*)src;
        float4 v1 = *(const float4*)(src + 4);
        tl[r][c8+0] = v0.x; tl[r][c8+1] = v0.y; tl[r][c8+2] = v0.z; tl[r][c8+3] = v0.w;
        tl[r][c8+4] = v1.x; tl[r][c8+5] = v1.y; tl[r][c8+6] = v1.z; tl[r][c8+7] = v1.w;

        // coef partial dots (reuse the registers just loaded)
        const float4* as = (const float4*)(a_src + h * HD + c8);
        const float4* ad = (const float4*)(a_dst + h * HD + c8);
        float4 a0 = as[0], a1 = as[1], d0 = ad[0], d1 = ad[1];
        float s = v0.x*a0.x + v0.y*a0.y + v0.z*a0.z + v0.w*a0.w
                + v1.x*a1.x + v1.y*a1.y + v1.z*a1.z + v1.w*a1.w;
        float tt = v0.x*d0.x + v0.y*d0.y + v0.z*d0.z + v0.w*d0.w
                 + v1.x*d1.x + v1.y*d1.y + v1.z*d1.z + v1.w*d1.w;
        s  += __shfl_xor_sync(0xffffffffu, s, 1);
        tt += __shfl_xor_sync(0xffffffffu, tt, 1);
        s  += __shfl_xor_sync(0xffffffffu, s, 2);
        tt += __shfl_xor_sync(0xffffffffu, tt, 2);
        s  += __shfl_xor_sync(0xffffffffu, s, 4);
        tt += __shfl_xor_sync(0xffffffffu, tt, 4);
        if ((t & 7) == 0) {
            const int idx = h * NN + n0 + r;
            g_P[idx] = __expf(s);
            g_p[idx] = __expf(0.2f * s);
            g_Q[idx] = __expf(tt);
            g_q[idx] = __expf(0.2f * tt);
        }
    }
    __syncthreads();
    const int d  = t >> 2;
    const int ns = (t & 3) * 8;
    uint32_t o0[4], o1[4];
#pragma unroll
    for (int k = 0; k < 4; k++) {
        o0[k] = tf32r(tl[ns + k][d]);
        o1[k] = tf32r(tl[ns + 4 + k][d]);
    }
    size_t o = (size_t)(h * HD + d) * NN + n0 + ns;
    *(uint4*)(g_hTf + o)     = make_uint4(o0[0], o0[1], o0[2], o0[3]);
    *(uint4*)(g_hTf + o + 4) = make_uint4(o1[0], o1[1], o1[2], o1[3]);
}

// ---------------- Kernel 4: tf32 MMA masked softmax-aggregate ----------------
__global__ __launch_bounds__(256, 2) void attn_kernel(float* __restrict__ out) {
    __shared__ __align__(16) float Bsm[2][HD * BROW];
    __shared__ __align__(8)  float2 QQ[2][KT];

    const int tid  = threadIdx.x;
    const int w    = tid >> 5;
    const int L    = tid & 31;
    const int head = blockIdx.y;
    const int i0   = blockIdx.x * MT;

    const int sd = tid >> 2;
    const int c4 = tid & 3;
    const float* hp = g_hTf + (size_t)(head * HD + sd) * NN;

    const int gr = L >> 2;
    const int c  = L & 3;
    const int irow0 = i0 + w * 16 + gr;
    const int irow1 = irow0 + 8;
    const float P0 = g_P[head * NN + irow0];
    const float p0 = g_p[head * NN + irow0];
    const float P1 = g_P[head * NN + irow1];
    const float p1 = g_p[head * NN + irow1];
    const unsigned* mrow0 = g_mask + (size_t)irow0 * MW;
    const unsigned* mrow1 = g_mask + (size_t)irow1 * MW;

    float acc[8][4];
#pragma unroll
    for (int n = 0; n < 8; n++)
#pragma unroll
        for (int k = 0; k < 4; k++) acc[n][k] = 0.f;
    float z0 = 0.f, z1 = 0.f;

    float4 nv0 = *(const float4*)(hp + c4 * 8);
    float4 nv1 = *(const float4*)(hp + c4 * 8 + 4);
    unsigned nm0 = mrow0[0];
    unsigned nm1 = mrow1[0];
    float nQ = 0.f, nq = 0.f;
    if (tid < KT) {
        nQ = g_Q[head * NN + tid];
        nq = g_q[head * NN + tid];
    }

    for (int t = 0; t < NTILES; t++) {
        const int buf = t & 1;
        {
            float* base = &Bsm[buf][sd * BROW];
            const int s0 = 2 * c4;
            base[0 * 8 + s0]     = nv0.x;
            base[1 * 8 + s0]     = nv0.y;
            base[2 * 8 + s0]     = nv0.z;
            base[3 * 8 + s0]     = nv0.w;
            base[0 * 8 + s0 + 1] = nv1.x;
            base[1 * 8 + s0 + 1] = nv1.y;
            base[2 * 8 + s0 + 1] = nv1.z;
            base[3 * 8 + s0 + 1] = nv1.w;
        }
        if (tid < KT) QQ[buf][tid] = make_float2(nQ, nq);
        const unsigned mw0 = nm0;
        const unsigned mw1 = nm1;
        __syncthreads();

        if (t + 1 < NTILES) {
            const int j0 = (t + 1) * KT;
            nv0 = *(const float4*)(hp + j0 + c4 * 8);
            nv1 = *(const float4*)(hp + j0 + c4 * 8 + 4);
            nm0 = mrow0[t + 1];
            nm1 = mrow1[t + 1];
            if (tid < KT) {
                nQ = g_Q[head * NN + j0 + tid];
                nq = g_q[head * NN + j0 + tid];
            }
        }

        uint32_t A[4][4];
#pragma unroll
        for (int s = 0; s < 4; s++) {
            const int ja = 8 * s + c;
            const int jb = ja + 4;
            float2 qa = QQ[buf][ja];
            float2 qb = QQ[buf][jb];
            float wa0 = fmaxf(P0 * qa.x, p0 * qa.y); wa0 = ((mw0 >> ja) & 1u) ? wa0 : 0.f;
            float wa1 = fmaxf(P1 * qa.x, p1 * qa.y); wa1 = ((mw1 >> ja) & 1u) ? wa1 : 0.f;
            float wb0 = fmaxf(P0 * qb.x, p0 * qb.y); wb0 = ((mw0 >> jb) & 1u) ? wb0 : 0.f;
            float wb1 = fmaxf(P1 * qb.x, p1 * qb.y); wb1 = ((mw1 >> jb) & 1u) ? wb1 : 0.f;
            A[s][0] = tf32r(wa0);
            A[s][1] = tf32r(wa1);
            A[s][2] = tf32r(wb0);
            A[s][3] = tf32r(wb1);
            z0 += __uint_as_float(A[s][0]) + __uint_as_float(A[s][2]);
            z1 += __uint_as_float(A[s][1]) + __uint_as_float(A[s][3]);
        }

#pragma unroll
        for (int nt = 0; nt < 8; nt++) {
            const float4* bp = (const float4*)(&Bsm[buf][(nt * 8 + gr) * BROW + c * 8]);
            float4 v0 = bp[0];
            float4 v1 = bp[1];
            mma_tf32(acc[nt], A[0], __float_as_uint(v0.x), __float_as_uint(v0.y));
            mma_tf32(acc[nt], A[1], __float_as_uint(v0.z), __float_as_uint(v0.w));
            mma_tf32(acc[nt], A[2], __float_as_uint(v1.x), __float_as_uint(v1.y));
            mma_tf32(acc[nt], A[3], __float_as_uint(v1.z), __float_as_uint(v1.w));
        }
        __syncthreads();
    }

    z0 += __shfl_xor_sync(0xffffffffu, z0, 1);
    z0 += __shfl_xor_sync(0xffffffffu, z0, 2);
    z1 += __shfl_xor_sync(0xffffffffu, z1, 1);
    z1 += __shfl_xor_sync(0xffffffffu, z1, 2);
    const float iz0 = 1.0f / z0;
    const float iz1 = 1.0f / z1;

    const int cb = c * 2;
    float* o0 = out + (size_t)irow0 * OF + head * HD + cb;
    float* o1 = out + (size_t)irow1 * OF + head * HD + cb;
#pragma unroll
    for (int nt = 0; nt < 8; nt++) {
        *(float2*)(o0 + nt * 8) = make_float2(acc[nt][0] * iz0, acc[nt][1] * iz0);
        *(float2*)(o1 + nt * 8) = make_float2(acc[nt][2] * iz1, acc[nt][3] * iz1);
    }
}

// ---------------- launch ----------------
extern "C" void kernel_launch(void* const* d_in, const int* in_sizes, int n_in,
                              void* d_out, int out_size) {
    const float* x     = (const float*)d_in[0];
    const int*   adj   = (const int*)d_in[1];
    const float* W     = (const float*)d_in[2];
    const float* a_src = (const float*)d_in[3];
    const float* a_dst = (const float*)d_in[4];
    float* out = (float*)d_out;

    __nv_bfloat16 *x1, *x2, *w1, *w2;
    cudaGetSymbolAddress((void**)&x1, g_X1);
    cudaGetSymbolAddress((void**)&x2, g_X2);
    cudaGetSymbolAddress((void**)&w1, g_W1);
    cudaGetSymbolAddress((void**)&w2, g_W2);

    fsplit_kernel<<<(NN * INF) / 1024, 256>>>(x, x1, x2);
    fsplit_kernel<<<(OF * INF) / 1024, 256>>>(W, w1, w2);
    mask_kernel<<<(NN * (NN / 256) * 32) / 256, 256>>>(adj);
    gemm_kernel<<<dim3(NN / 64, OF / 128), 256>>>();
    htrans_kernel<<<dim3(NN / 32, NH), 256>>>(a_src, a_dst);
    attn_kernel<<<dim3(NN / MT, NH), 256>>>(out);
}

// round 9
// speedup vs baseline: 2.0552x; 1.1902x over previous
#include <cuda_runtime.h>
#include <cuda_bf16.h>
#include <cstdint>

#define NN   3072
#define INF  512
#define NH   8
#define HD   64
#define OF   512   // NH*HD
#define MW   96    // mask words per row
#define KT   32    // attn j tile
#define MT   192   // attn i tile per CTA (12 warps)
#define NTILES (NN / KT)
#define BROW 36    // B smem row pitch in floats (144B, conflict-free)

// ---------------- scratch ----------------
__device__ float         g_h[NN * OF];
__device__ float         g_P[NH * NN];
__device__ float         g_p[NH * NN];
__device__ float         g_Q[NH * NN];
__device__ float         g_q[NH * NN];
__device__ unsigned      g_mask[NN * MW];
__device__ float         g_hTf[NH * HD * NN];      // [h][d][n], tf32-rounded fp32
__device__ __nv_bfloat16 g_X1[NN * INF];
__device__ __nv_bfloat16 g_X2[NN * INF];
__device__ __nv_bfloat16 g_W1[OF * INF];
__device__ __nv_bfloat16 g_W2[OF * INF];

__device__ __forceinline__ uint32_t smem_u32(const void* p) {
    uint32_t a;
    asm("{ .reg .u64 t; cvta.to.shared.u64 t, %1; cvt.u32.u64 %0, t; }" : "=r"(a) : "l"(p));
    return a;
}

__device__ __forceinline__ void mma_bf16(float* c, const uint32_t* a, uint32_t b0, uint32_t b1) {
    asm volatile(
        "mma.sync.aligned.m16n8k16.row.col.f32.bf16.bf16.f32 "
        "{%0,%1,%2,%3}, {%4,%5,%6,%7}, {%8,%9}, {%0,%1,%2,%3};"
        : "+f"(c[0]), "+f"(c[1]), "+f"(c[2]), "+f"(c[3])
        : "r"(a[0]), "r"(a[1]), "r"(a[2]), "r"(a[3]), "r"(b0), "r"(b1));
}

__device__ __forceinline__ void mma_tf32(float* c, const uint32_t* a, uint32_t b0, uint32_t b1) {
    asm volatile(
        "mma.sync.aligned.m16n8k8.row.col.f32.tf32.tf32.f32 "
        "{%0,%1,%2,%3}, {%4,%5,%6,%7}, {%8,%9}, {%0,%1,%2,%3};"
        : "+f"(c[0]), "+f"(c[1]), "+f"(c[2]), "+f"(c[3])
        : "r"(a[0]), "r"(a[1]), "r"(a[2]), "r"(a[3]), "r"(b0), "r"(b1));
}

__device__ __forceinline__ void ldmx4(uint32_t* r, uint32_t addr) {
    asm volatile("ldmatrix.sync.aligned.m8n8.x4.shared.b16 {%0,%1,%2,%3}, [%4];"
                 : "=r"(r[0]), "=r"(r[1]), "=r"(r[2]), "=r"(r[3]) : "r"(addr));
}

__device__ __forceinline__ void split2(float w0, float w1, uint32_t& hi, uint32_t& lo) {
    uint32_t h;
    asm("cvt.rn.bf16x2.f32 %0, %1, %2;" : "=r"(h) : "f"(w1), "f"(w0));
    float r0 = w0 - __uint_as_float(h << 16);
    float r1 = w1 - __uint_as_float(h & 0xffff0000u);
    uint32_t l;
    asm("cvt.rn.bf16x2.f32 %0, %1, %2;" : "=r"(l) : "f"(r1), "f"(r0));
    hi = h; lo = l;
}

__device__ __forceinline__ uint32_t tf32r(float v) {
    uint32_t d;
    asm("cvt.rna.tf32.f32 %0, %1;" : "=r"(d) : "f"(v));
    return d;
}

// ---------------- Kernel 0: fp32 -> bf16 hi/lo split ----------------
__global__ __launch_bounds__(256) void fsplit_kernel(const float* __restrict__ src,
                                                     __nv_bfloat16* __restrict__ dhi,
                                                     __nv_bfloat16* __restrict__ dlo) {
    const int idx = (blockIdx.x * blockDim.x + threadIdx.x) * 4;
    float4 v = *(const float4*)(src + idx);
    uint32_t h0, h1, l0, l1;
    split2(v.x, v.y, h0, l0);
    split2(v.z, v.w, h1, l1);
    *(uint2*)(dhi + idx) = make_uint2(h0, h1);
    *(uint2*)(dlo + idx) = make_uint2(l0, l1);
}

// ---------------- Kernel 1: g_h = X @ W^T (bf16-split HMMA) ----------------
// CTA = 96m x 128n, BK=32, grid (32, 4) = 128 CTAs -> single wave.
// 12 warps as 3(m) x 4(n), warp = 32m x 32n.
__global__ __launch_bounds__(384) void gemm_kernel() {
    __shared__ __align__(16) unsigned char Ah[2][96 * 64];    // 12KB
    __shared__ __align__(16) unsigned char Al[2][96 * 64];
    __shared__ __align__(16) unsigned char Bh[2][128 * 64];   // 16KB
    __shared__ __align__(16) unsigned char Bl[2][128 * 64];

    const int tid = threadIdx.x;
    const int w   = tid >> 5;
    const int L   = tid & 31;
    const int bm  = blockIdx.x * 96;
    const int bn  = blockIdx.y * 128;

    // staging: A = 96 rows x 4 chunks = 384 tasks (1/thread);
    //          B = 128 rows x 4 chunks = 512 tasks (1/thread + tid<128 second)
    const int arow   = tid >> 2;
    const int achunk = tid & 3;
    const uint32_t aoff = (uint32_t)(arow * 64 + ((achunk ^ ((arow >> 1) & 3)) << 4));
    const int brow0  = tid >> 2;                 // 0..95
    const int bchunk = tid & 3;
    const uint32_t boff0 = (uint32_t)(brow0 * 64 + ((bchunk ^ ((brow0 >> 1) & 3)) << 4));
    const int brow1  = 96 + (tid >> 2);          // valid when tid < 128
    const uint32_t boff1 = (uint32_t)(brow1 * 64 + ((bchunk ^ ((brow1 >> 1) & 3)) << 4));
    const bool hasB1 = tid < 128;

    const int warp_m = (w >> 2) * 32;            // 0,32,64
    const int warp_n = (w & 3) * 32;

    float acc[2][4][4];
#pragma unroll
    for (int mg = 0; mg < 2; mg++)
#pragma unroll
        for (int ng = 0; ng < 4; ng++)
#pragma unroll
            for (int k = 0; k < 4; k++) acc[mg][ng][k] = 0.f;

    uint4 xa_h, xa_l, wb_h0, wb_l0, wb_h1, wb_l1;
    {
        const size_t ao = (size_t)(bm + arow) * INF + achunk * 8;
        xa_h = *(const uint4*)(g_X1 + ao);
        xa_l = *(const uint4*)(g_X2 + ao);
        const size_t bo0 = (size_t)(bn + brow0) * INF + bchunk * 8;
        wb_h0 = *(const uint4*)(g_W1 + bo0);
        wb_l0 = *(const uint4*)(g_W2 + bo0);
        if (hasB1) {
            const size_t bo1 = (size_t)(bn + brow1) * INF + bchunk * 8;
            wb_h1 = *(const uint4*)(g_W1 + bo1);
            wb_l1 = *(const uint4*)(g_W2 + bo1);
        }
    }

    for (int it = 0; it < INF / 32; it++) {
        const int buf = it & 1;
        *(uint4*)&Ah[buf][aoff]  = xa_h;
        *(uint4*)&Al[buf][aoff]  = xa_l;
        *(uint4*)&Bh[buf][boff0] = wb_h0;
        *(uint4*)&Bl[buf][boff0] = wb_l0;
        if (hasB1) {
            *(uint4*)&Bh[buf][boff1] = wb_h1;
            *(uint4*)&Bl[buf][boff1] = wb_l1;
        }
        __syncthreads();

        if (it + 1 < INF / 32) {
            const int k0 = (it + 1) * 32;
            const size_t ao = (size_t)(bm + arow) * INF + k0 + achunk * 8;
            xa_h = *(const uint4*)(g_X1 + ao);
            xa_l = *(const uint4*)(g_X2 + ao);
            const size_t bo0 = (size_t)(bn + brow0) * INF + k0 + bchunk * 8;
            wb_h0 = *(const uint4*)(g_W1 + bo0);
            wb_l0 = *(const uint4*)(g_W2 + bo0);
            if (hasB1) {
                const size_t bo1 = (size_t)(bn + brow1) * INF + k0 + bchunk * 8;
                wb_h1 = *(const uint4*)(g_W1 + bo1);
                wb_l1 = *(const uint4*)(g_W2 + bo1);
            }
        }

        const uint32_t aAh = smem_u32(&Ah[buf][0]);
        const uint32_t aAl = smem_u32(&Al[buf][0]);
        const uint32_t aBh = smem_u32(&Bh[buf][0]);
        const uint32_t aBl = smem_u32(&Bl[buf][0]);

        uint32_t bh[4][4], bl[4][4];
#pragma unroll
        for (int ng = 0; ng < 4; ng++) {
            const int row = warp_n + ng * 8 + (L & 7);
            const int ch  = L >> 3;
            const uint32_t off = (uint32_t)(row * 64 + ((ch ^ ((row >> 1) & 3)) << 4));
            ldmx4(bh[ng], aBh + off);
            ldmx4(bl[ng], aBl + off);
        }
        uint32_t ah[2][2][4], al[2][2][4];
#pragma unroll
        for (int mg = 0; mg < 2; mg++)
#pragma unroll
            for (int ks = 0; ks < 2; ks++) {
                const int mat = L >> 3;
                const int row = warp_m + mg * 16 + (L & 7) + (mat & 1) * 8;
                const int ch  = ks * 2 + (mat >> 1);
                const uint32_t off = (uint32_t)(row * 64 + ((ch ^ ((row >> 1) & 3)) << 4));
                ldmx4(ah[mg][ks], aAh + off);
                ldmx4(al[mg][ks], aAl + off);
            }

#pragma unroll
        for (int mg = 0; mg < 2; mg++)
#pragma unroll
            for (int ng = 0; ng < 4; ng++)
#pragma unroll
                for (int ks = 0; ks < 2; ks++) {
                    mma_bf16(acc[mg][ng], ah[mg][ks], bh[ng][2*ks], bh[ng][2*ks+1]);
                    mma_bf16(acc[mg][ng], ah[mg][ks], bl[ng][2*ks], bl[ng][2*ks+1]);
                    mma_bf16(acc[mg][ng], al[mg][ks], bh[ng][2*ks], bh[ng][2*ks+1]);
                }
        __syncthreads();
    }

#pragma unroll
    for (int mg = 0; mg < 2; mg++)
#pragma unroll
        for (int ng = 0; ng < 4; ng++) {
            const int row = bm + warp_m + mg * 16 + (L >> 2);
            const int col = bn + warp_n + ng * 8 + (L & 3) * 2;
            *(float2*)(g_h + (size_t)row * OF + col)       = make_float2(acc[mg][ng][0], acc[mg][ng][1]);
            *(float2*)(g_h + (size_t)(row + 8) * OF + col) = make_float2(acc[mg][ng][2], acc[mg][ng][3]);
        }
}

// ---------------- Kernel 3: adjacency (+diag) bitmask, MLP=2 ----------------
__global__ __launch_bounds__(256) void mask_kernel(const int* __restrict__ adj) {
    const int gw = (blockIdx.x * blockDim.x + threadIdx.x) >> 5;
    const int L  = threadIdx.x & 31;
    const int i  = gw / (NN / 256);
    const int sp = gw % (NN / 256);
    const int c0 = sp * 256 + L * 4;
    const int c1 = c0 + 128;
    const int4 v0 = *(const int4*)(adj + (size_t)i * NN + c0);
    const int4 v1 = *(const int4*)(adj + (size_t)i * NN + c1);
    unsigned nib0 = ((v0.x != 0 || c0     == i) ? 1u : 0u)
                  | ((v0.y != 0 || c0 + 1 == i) ? 2u : 0u)
                  | ((v0.z != 0 || c0 + 2 == i) ? 4u : 0u)
                  | ((v0.w != 0 || c0 + 3 == i) ? 8u : 0u);
    unsigned nib1 = ((v1.x != 0 || c1     == i) ? 1u : 0u)
                  | ((v1.y != 0 || c1 + 1 == i) ? 2u : 0u)
                  | ((v1.z != 0 || c1 + 2 == i) ? 4u : 0u)
                  | ((v1.w != 0 || c1 + 3 == i) ? 8u : 0u);
    unsigned a = nib0 << ((L & 7) * 4);
    unsigned b = nib1 << ((L & 7) * 4);
    a |= __shfl_xor_sync(0xffffffffu, a, 1);
    b |= __shfl_xor_sync(0xffffffffu, b, 1);
    a |= __shfl_xor_sync(0xffffffffu, a, 2);
    b |= __shfl_xor_sync(0xffffffffu, b, 2);
    a |= __shfl_xor_sync(0xffffffffu, a, 4);
    b |= __shfl_xor_sync(0xffffffffu, b, 4);
    if ((L & 7) == 0) {
        g_mask[i * MW + sp * 8 + (L >> 3)]     = a;
        g_mask[i * MW + sp * 8 + 4 + (L >> 3)] = b;
    }
}

// ---------------- Kernel 3b: fused transpose(tf32) + coef ----------------
__global__ __launch_bounds__(256) void htrans_kernel(const float* __restrict__ a_src,
                                                     const float* __restrict__ a_dst) {
    __shared__ float tl[32][65];
    const int h  = blockIdx.y;
    const int n0 = blockIdx.x * 32;
    const int t  = threadIdx.x;
    const int r  = t >> 3;
    const int c8 = (t & 7) * 8;
    {
        const float* src = g_h + (size_t)(n0 + r) * OF + h * HD + c8;
        float4 v0 = *(const float4*)src;
        float4 v1 = *(const float4*)(src + 4);
        tl[r][c8+0] = v0.x; tl[r][c8+1] = v0.y; tl[r][c8+2] = v0.z; tl[r][c8+3] = v0.w;
        tl[r][c8+4] = v1.x; tl[r][c8+5] = v1.y; tl[r][c8+6] = v1.z; tl[r][c8+7] = v1.w;

        const float4* as = (const float4*)(a_src + h * HD + c8);
        const float4* ad = (const float4*)(a_dst + h * HD + c8);
        float4 a0 = as[0], a1 = as[1], d0 = ad[0], d1 = ad[1];
        float s = v0.x*a0.x + v0.y*a0.y + v0.z*a0.z + v0.w*a0.w
                + v1.x*a1.x + v1.y*a1.y + v1.z*a1.z + v1.w*a1.w;
        float tt = v0.x*d0.x + v0.y*d0.y + v0.z*d0.z + v0.w*d0.w
                 + v1.x*d1.x + v1.y*d1.y + v1.z*d1.z + v1.w*d1.w;
        s  += __shfl_xor_sync(0xffffffffu, s, 1);
        tt += __shfl_xor_sync(0xffffffffu, tt, 1);
        s  += __shfl_xor_sync(0xffffffffu, s, 2);
        tt += __shfl_xor_sync(0xffffffffu, tt, 2);
        s  += __shfl_xor_sync(0xffffffffu, s, 4);
        tt += __shfl_xor_sync(0xffffffffu, tt, 4);
        if ((t & 7) == 0) {
            const int idx = h * NN + n0 + r;
            g_P[idx] = __expf(s);
            g_p[idx] = __expf(0.2f * s);
            g_Q[idx] = __expf(tt);
            g_q[idx] = __expf(0.2f * tt);
        }
    }
    __syncthreads();
    const int d  = t >> 2;
    const int ns = (t & 3) * 8;
    uint32_t o0[4], o1[4];
#pragma unroll
    for (int k = 0; k < 4; k++) {
        o0[k] = tf32r(tl[ns + k][d]);
        o1[k] = tf32r(tl[ns + 4 + k][d]);
    }
    size_t o = (size_t)(h * HD + d) * NN + n0 + ns;
    *(uint4*)(g_hTf + o)     = make_uint4(o0[0], o0[1], o0[2], o0[3]);
    *(uint4*)(g_hTf + o + 4) = make_uint4(o1[0], o1[1], o1[2], o1[3]);
}

// ---------------- Kernel 4: tf32 MMA masked softmax-aggregate ----------------
// CTA = 192 i x 1 head, 12 warps, grid (16, 8) = 128 CTAs -> single wave.
__global__ __launch_bounds__(384) void attn_kernel(float* __restrict__ out) {
    __shared__ __align__(16) float Bsm[2][HD * BROW];
    __shared__ __align__(8)  float2 QQ[2][KT];

    const int tid  = threadIdx.x;
    const int w    = tid >> 5;
    const int L    = tid & 31;
    const int head = blockIdx.y;
    const int i0   = blockIdx.x * MT;

    // staging role (first 256 threads stage B)
    const int sd = tid >> 2;            // 0..95, valid rows < 64
    const int c4 = tid & 3;
    const bool stager = tid < 256;
    const float* hp = g_hTf + (size_t)(head * HD + (sd & 63)) * NN;

    // fragment role
    const int gr = L >> 2;
    const int c  = L & 3;
    const int irow0 = i0 + w * 16 + gr;
    const int irow1 = irow0 + 8;
    const float P0 = g_P[head * NN + irow0];
    const float p0 = g_p[head * NN + irow0];
    const float P1 = g_P[head * NN + irow1];
    const float p1 = g_p[head * NN + irow1];
    const unsigned* mrow0 = g_mask + (size_t)irow0 * MW;
    const unsigned* mrow1 = g_mask + (size_t)irow1 * MW;

    float acc[8][4];
#pragma unroll
    for (int n = 0; n < 8; n++)
#pragma unroll
        for (int k = 0; k < 4; k++) acc[n][k] = 0.f;
    float z0 = 0.f, z1 = 0.f;

    float4 nv0, nv1;
    if (stager) {
        nv0 = *(const float4*)(hp + c4 * 8);
        nv1 = *(const float4*)(hp + c4 * 8 + 4);
    }
    unsigned nm0 = mrow0[0];
    unsigned nm1 = mrow1[0];
    float nQ = 0.f, nq = 0.f;
    if (tid < KT) {
        nQ = g_Q[head * NN + tid];
        nq = g_q[head * NN + tid];
    }

    for (int t = 0; t < NTILES; t++) {
        const int buf = t & 1;
        if (stager) {
            float* base = &Bsm[buf][sd * BROW];
            const int s0 = 2 * c4;
            base[0 * 8 + s0]     = nv0.x;
            base[1 * 8 + s0]     = nv0.y;
            base[2 * 8 + s0]     = nv0.z;
            base[3 * 8 + s0]     = nv0.w;
            base[0 * 8 + s0 + 1] = nv1.x;
            base[1 * 8 + s0 + 1] = nv1.y;
            base[2 * 8 + s0 + 1] = nv1.z;
            base[3 * 8 + s0 + 1] = nv1.w;
        }
        if (tid < KT) QQ[buf][tid] = make_float2(nQ, nq);
        const unsigned mw0 = nm0;
        const unsigned mw1 = nm1;
        __syncthreads();

        if (t + 1 < NTILES) {
            const int j0 = (t + 1) * KT;
            if (stager) {
                nv0 = *(const float4*)(hp + j0 + c4 * 8);
                nv1 = *(const float4*)(hp + j0 + c4 * 8 + 4);
            }
            nm0 = mrow0[t + 1];
            nm1 = mrow1[t + 1];
            if (tid < KT) {
                nQ = g_Q[head * NN + j0 + tid];
                nq = g_q[head * NN + j0 + tid];
            }
        }

        uint32_t A[4][4];
#pragma unroll
        for (int s = 0; s < 4; s++) {
            const int ja = 8 * s + c;
            const int jb = ja + 4;
            float2 qa = QQ[buf][ja];
            float2 qb = QQ[buf][jb];
            float wa0 = fmaxf(P0 * qa.x, p0 * qa.y); wa0 = ((mw0 >> ja) & 1u) ? wa0 : 0.f;
            float wa1 = fmaxf(P1 * qa.x, p1 * qa.y); wa1 = ((mw1 >> ja) & 1u) ? wa1 : 0.f;
            float wb0 = fmaxf(P0 * qb.x, p0 * qb.y); wb0 = ((mw0 >> jb) & 1u) ? wb0 : 0.f;
            float wb1 = fmaxf(P1 * qb.x, p1 * qb.y); wb1 = ((mw1 >> jb) & 1u) ? wb1 : 0.f;
            A[s][0] = tf32r(wa0);
            A[s][1] = tf32r(wa1);
            A[s][2] = tf32r(wb0);
            A[s][3] = tf32r(wb1);
            z0 += __uint_as_float(A[s][0]) + __uint_as_float(A[s][2]);
            z1 += __uint_as_float(A[s][1]) + __uint_as_float(A[s][3]);
        }

#pragma unroll
        for (int nt = 0; nt < 8; nt++) {
            const float4* bp = (const float4*)(&Bsm[buf][(nt * 8 + gr) * BROW + c * 8]);
            float4 v0 = bp[0];
            float4 v1 = bp[1];
            mma_tf32(acc[nt], A[0], __float_as_uint(v0.x), __float_as_uint(v0.y));
            mma_tf32(acc[nt], A[1], __float_as_uint(v0.z), __float_as_uint(v0.w));
            mma_tf32(acc[nt], A[2], __float_as_uint(v1.x), __float_as_uint(v1.y));
            mma_tf32(acc[nt], A[3], __float_as_uint(v1.z), __float_as_uint(v1.w));
        }
        __syncthreads();
    }

    z0 += __shfl_xor_sync(0xffffffffu, z0, 1);
    z0 += __shfl_xor_sync(0xffffffffu, z0, 2);
    z1 += __shfl_xor_sync(0xffffffffu, z1, 1);
    z1 += __shfl_xor_sync(0xffffffffu, z1, 2);
    const float iz0 = 1.0f / z0;
    const float iz1 = 1.0f / z1;

    const int cb = c * 2;
    float* o0 = out + (size_t)irow0 * OF + head * HD + cb;
    float* o1 = out + (size_t)irow1 * OF + head * HD + cb;
#pragma unroll
    for (int nt = 0; nt < 8; nt++) {
        *(float2*)(o0 + nt * 8) = make_float2(acc[nt][0] * iz0, acc[nt][1] * iz0);
        *(float2*)(o1 + nt * 8) = make_float2(acc[nt][2] * iz1, acc[nt][3] * iz1);
    }
}

// ---------------- launch ----------------
extern "C" void kernel_launch(void* const* d_in, const int* in_sizes, int n_in,
                              void* d_out, int out_size) {
    const float* x     = (const float*)d_in[0];
    const int*   adj   = (const int*)d_in[1];
    const float* W     = (const float*)d_in[2];
    const float* a_src = (const float*)d_in[3];
    const float* a_dst = (const float*)d_in[4];
    float* out = (float*)d_out;

    __nv_bfloat16 *x1, *x2, *w1, *w2;
    cudaGetSymbolAddress((void**)&x1, g_X1);
    cudaGetSymbolAddress((void**)&x2, g_X2);
    cudaGetSymbolAddress((void**)&w1, g_W1);
    cudaGetSymbolAddress((void**)&w2, g_W2);

    fsplit_kernel<<<(NN * INF) / 1024, 256>>>(x, x1, x2);
    fsplit_kernel<<<(OF * INF) / 1024, 256>>>(W, w1, w2);
    mask_kernel<<<(NN * (NN / 256) * 32) / 256, 256>>>(adj);
    gemm_kernel<<<dim3(NN / 96, OF / 128), 384>>>();
    htrans_kernel<<<dim3(NN / 32, NH), 256>>>(a_src, a_dst);
    attn_kernel<<<dim3(NN / MT, NH), 384>>>(out);
}